// round 1
// baseline (speedup 1.0000x reference)
#include <cuda_runtime.h>
#include <cstdint>

#define NNODE 10000
#define INC   256
#define HID   128      // 2*OUT_C
#define OUTC  64
#define NEDGE 640000

// ---------------- scratch (device globals; no allocations allowed) ----------
__device__ float g_h  [NNODE * INC];   // relu(x@Wt+bt)
__device__ float g_g1 [NNODE * HID];   // h @ W1_1
__device__ float g_s1 [NNODE * HID];   // scatter of w*g1[src]
__device__ float g_h2 [NNODE * HID];   // relu(h@W0_1 + s1 + b1)
__device__ float g_g2 [NNODE * HID];   // [h2@W1_mu | h2@W1_ls]
__device__ float g_s2 [NNODE * HID];   // scatter of w*g2[src]
__device__ float g_dinv[NNODE];
__device__ int   g_deg [NNODE];

// ---------------- init / degree / dinv --------------------------------------
__global__ void zero_kernel(float* s1, float* s2, int* deg) {
    int i = blockIdx.x * blockDim.x + threadIdx.x;
    if (i < NNODE * HID) { s1[i] = 0.f; s2[i] = 0.f; }
    if (i < NNODE) deg[i] = 0;
}

__global__ void deg_kernel(const int* __restrict__ src, int* __restrict__ deg) {
    int e = blockIdx.x * blockDim.x + threadIdx.x;
    if (e < NEDGE) atomicAdd(&deg[src[e]], 1);
}

__global__ void dinv_kernel(const int* __restrict__ deg, float* __restrict__ dinv) {
    int i = blockIdx.x * blockDim.x + threadIdx.x;
    if (i < NNODE) {
        int d = deg[i];
        dinv[i] = (d > 0) ? rsqrtf((float)d) : 0.f;
    }
}

// ---------------- big GEMM: h = relu(x @ Wt + bt) ---------------------------
// A [10000,10000], B [10000,256], C [10000,256]
// BM=128, BN=64, BK=16, 256 threads, 8x4 per thread.
__global__ __launch_bounds__(256) void gemm_big_kernel(
    const float* __restrict__ A, const float* __restrict__ B,
    const float* __restrict__ bias, float* __restrict__ C)
{
    const int M = NNODE, K = NNODE;
    __shared__ float  sA[16][132];      // [k][m], padded
    __shared__ float4 sB[16][16];       // [k][n/4]

    const int tid  = threadIdx.x;
    const int row0 = blockIdx.y * 128;
    const int col0 = blockIdx.x * 64;

    const int tx = tid & 15;            // 16 col-groups of 4
    const int ty = tid >> 4;            // 16 row-groups of 8

    // load-index precompute
    const int ar0 = (tid * 2) >> 2;        // A: two float4 per thread
    const int ac0 = (tid * 2) & 3;
    const int ar1 = (tid * 2 + 1) >> 2;
    const int ac1 = (tid * 2 + 1) & 3;
    const int br  = tid >> 4;              // B: one float4 per thread
    const int bc  = tid & 15;

    const float4* A4 = (const float4*)A;
    const float4* B4 = (const float4*)B;

    float acc[8][4];
#pragma unroll
    for (int i = 0; i < 8; i++)
#pragma unroll
        for (int j = 0; j < 4; j++) acc[i][j] = 0.f;

    const int KT = K / 16;   // 625

    // preload tile 0
    {
        const int k0 = 0;
        float4 va0 = make_float4(0.f,0.f,0.f,0.f), va1 = va0;
        int r;
        r = row0 + ar0; if (r < M) va0 = A4[r * (K/4) + (k0>>2) + ac0];
        r = row0 + ar1; if (r < M) va1 = A4[r * (K/4) + (k0>>2) + ac1];
        sA[ac0*4+0][ar0]=va0.x; sA[ac0*4+1][ar0]=va0.y; sA[ac0*4+2][ar0]=va0.z; sA[ac0*4+3][ar0]=va0.w;
        sA[ac1*4+0][ar1]=va1.x; sA[ac1*4+1][ar1]=va1.y; sA[ac1*4+2][ar1]=va1.z; sA[ac1*4+3][ar1]=va1.w;
        sB[br][bc] = B4[(k0 + br) * 64 + (col0>>2) + bc];
    }
    __syncthreads();

    for (int kt = 0; kt < KT; kt++) {
        float4 na0, na1, nb;
        const bool more = (kt + 1 < KT);
        if (more) {
            const int k0 = (kt + 1) * 16;
            na0 = make_float4(0.f,0.f,0.f,0.f); na1 = na0;
            int r;
            r = row0 + ar0; if (r < M) na0 = A4[r * (K/4) + (k0>>2) + ac0];
            r = row0 + ar1; if (r < M) na1 = A4[r * (K/4) + (k0>>2) + ac1];
            nb = B4[(k0 + br) * 64 + (col0>>2) + bc];
        }

#pragma unroll
        for (int kk = 0; kk < 16; kk++) {
            float4 b = sB[kk][tx];
            const float* ap = &sA[kk][ty * 8];
            float4 a0 = *(const float4*)ap;
            float4 a1 = *(const float4*)(ap + 4);
            float av[8] = {a0.x,a0.y,a0.z,a0.w,a1.x,a1.y,a1.z,a1.w};
#pragma unroll
            for (int i = 0; i < 8; i++) {
                acc[i][0] += av[i] * b.x;
                acc[i][1] += av[i] * b.y;
                acc[i][2] += av[i] * b.z;
                acc[i][3] += av[i] * b.w;
            }
        }
        __syncthreads();
        if (more) {
            sA[ac0*4+0][ar0]=na0.x; sA[ac0*4+1][ar0]=na0.y; sA[ac0*4+2][ar0]=na0.z; sA[ac0*4+3][ar0]=na0.w;
            sA[ac1*4+0][ar1]=na1.x; sA[ac1*4+1][ar1]=na1.y; sA[ac1*4+2][ar1]=na1.z; sA[ac1*4+3][ar1]=na1.w;
            sB[br][bc] = nb;
            __syncthreads();
        }
    }

    // epilogue: bias + relu
    float4 bb = ((const float4*)bias)[(col0 >> 2) + tx];
    float4* C4 = (float4*)C;
#pragma unroll
    for (int i = 0; i < 8; i++) {
        int r = row0 + ty * 8 + i;
        if (r < M) {
            float4 o;
            o.x = fmaxf(acc[i][0] + bb.x, 0.f);
            o.y = fmaxf(acc[i][1] + bb.y, 0.f);
            o.z = fmaxf(acc[i][2] + bb.z, 0.f);
            o.w = fmaxf(acc[i][3] + bb.w, 0.f);
            C4[r * 64 + (col0 >> 2) + tx] = o;
        }
    }
}

// ---------------- small GEMM with fused epilogue ----------------------------
// C[M,NC] = A[M,K] @ B[K,NC] (+ addend[r*ld_add .. ]) (+ bias) (relu?)
// blockDim = (NC/4, 8). Each thread: 4 cols of one row.
template<int K, int NC>
__global__ void gemm_small_kernel(
    const float* __restrict__ A, const float* __restrict__ B,
    const float* __restrict__ bias, const float* __restrict__ addend,
    int ld_add, float* __restrict__ C, int ldc, int M, int do_relu)
{
    __shared__ float sA[8][K];
    const int tx = threadIdx.x;            // 0..NC/4-1
    const int ty = threadIdx.y;            // 0..7
    const int nt = (NC / 4) * 8;
    const int tid = ty * (NC / 4) + tx;
    const int row0 = blockIdx.x * 8;

    // cooperative load of 8 rows of A
    const float4* A4 = (const float4*)A;
    const int nf4 = 8 * K / 4;
    for (int i = tid; i < nf4; i += nt) {
        int r = i / (K / 4);
        int c = i - r * (K / 4);
        int gr = row0 + r;
        float4 v = make_float4(0.f,0.f,0.f,0.f);
        if (gr < M) v = A4[gr * (K / 4) + c];
        ((float4*)&sA[r][0])[c] = v;
    }
    __syncthreads();

    const float4* B4 = (const float4*)B;
    float4 acc = make_float4(0.f,0.f,0.f,0.f);
#pragma unroll 8
    for (int k = 0; k < K; k++) {
        float a = sA[ty][k];
        float4 b = __ldg(&B4[k * (NC / 4) + tx]);
        acc.x += a * b.x; acc.y += a * b.y; acc.z += a * b.z; acc.w += a * b.w;
    }

    int r = row0 + ty;
    if (r < M) {
        if (addend) {
            float4 ad = *(const float4*)(addend + (size_t)r * ld_add + tx * 4);
            acc.x += ad.x; acc.y += ad.y; acc.z += ad.z; acc.w += ad.w;
        }
        if (bias) {
            float4 bb = ((const float4*)bias)[tx];
            acc.x += bb.x; acc.y += bb.y; acc.z += bb.z; acc.w += bb.w;
        }
        if (do_relu) {
            acc.x = fmaxf(acc.x, 0.f); acc.y = fmaxf(acc.y, 0.f);
            acc.z = fmaxf(acc.z, 0.f); acc.w = fmaxf(acc.w, 0.f);
        }
        *(float4*)(C + (size_t)r * ldc + tx * 4) = acc;
    }
}

// ---------------- edge scatter: S[dst] += (-dinv[src]*dinv[dst]) * G[src] ---
// 128 features per node; one warp per edge, 1 float4 per lane.
__global__ void scatter_kernel(
    const int* __restrict__ src, const int* __restrict__ dst,
    const float* __restrict__ dinv, const float* __restrict__ G,
    float* __restrict__ S)
{
    int t = blockIdx.x * blockDim.x + threadIdx.x;
    int e = t >> 5;
    int lane = t & 31;
    if (e >= NEDGE) return;
    int s = src[e], d = dst[e];
    float w = -dinv[s] * dinv[d];
    const float4* G4 = (const float4*)G;
    float4 v = __ldg(&G4[s * 32 + lane]);
    float* p = &S[d * HID + lane * 4];
    atomicAdd(p + 0, v.x * w);
    atomicAdd(p + 1, v.y * w);
    atomicAdd(p + 2, v.z * w);
    atomicAdd(p + 3, v.w * w);
}

// ---------------- launch -----------------------------------------------------
extern "C" void kernel_launch(void* const* d_in, const int* in_sizes, int n_in,
                              void* d_out, int out_size)
{
    const float* x     = (const float*)d_in[0];
    const int*   ei    = (const int*)  d_in[1];
    const float* Wt    = (const float*)d_in[2];
    const float* bt    = (const float*)d_in[3];
    const float* W0_1  = (const float*)d_in[4];
    const float* W1_1  = (const float*)d_in[5];
    const float* b1    = (const float*)d_in[6];
    const float* W0_mu = (const float*)d_in[7];
    const float* W1_mu = (const float*)d_in[8];
    const float* b_mu  = (const float*)d_in[9];
    const float* W0_ls = (const float*)d_in[10];
    const float* W1_ls = (const float*)d_in[11];
    const float* b_ls  = (const float*)d_in[12];
    float* out = (float*)d_out;

    const int* src = ei;
    const int* dst = ei + NEDGE;

    float *hP, *g1P, *s1P, *h2P, *g2P, *s2P, *dinvP;
    int* degP;
    cudaGetSymbolAddress((void**)&hP,   g_h);
    cudaGetSymbolAddress((void**)&g1P,  g_g1);
    cudaGetSymbolAddress((void**)&s1P,  g_s1);
    cudaGetSymbolAddress((void**)&h2P,  g_h2);
    cudaGetSymbolAddress((void**)&g2P,  g_g2);
    cudaGetSymbolAddress((void**)&s2P,  g_s2);
    cudaGetSymbolAddress((void**)&dinvP, g_dinv);
    cudaGetSymbolAddress((void**)&degP,  g_deg);

    // 1. zero scratch + degree accumulators
    zero_kernel<<<(NNODE * HID + 255) / 256, 256>>>(s1P, s2P, degP);
    // 2. degrees + dinv
    deg_kernel<<<(NEDGE + 255) / 256, 256>>>(src, degP);
    dinv_kernel<<<(NNODE + 255) / 256, 256>>>(degP, dinvP);
    // 3. h = relu(x @ Wt + bt)
    {
        dim3 grid(INC / 64, (NNODE + 127) / 128);
        gemm_big_kernel<<<grid, 256>>>(x, Wt, bt, hP);
    }
    // 4. g1 = h @ W1_1
    {
        dim3 blk(HID / 4, 8);
        gemm_small_kernel<INC, HID><<<NNODE / 8, blk>>>(hP, W1_1, nullptr, nullptr, 0, g1P, HID, NNODE, 0);
    }
    // 5. s1 = scatter(w * g1[src] -> dst)
    scatter_kernel<<<(NEDGE * 32) / 256, 256>>>(src, dst, dinvP, g1P, s1P);
    // 6. h2 = relu(h @ W0_1 + s1 + b1)
    {
        dim3 blk(HID / 4, 8);
        gemm_small_kernel<INC, HID><<<NNODE / 8, blk>>>(hP, W0_1, b1, s1P, HID, h2P, HID, NNODE, 1);
    }
    // 7. g2 = [h2 @ W1_mu | h2 @ W1_ls]
    {
        dim3 blk(OUTC / 4, 8);
        gemm_small_kernel<HID, OUTC><<<NNODE / 8, blk>>>(h2P, W1_mu, nullptr, nullptr, 0, g2P,      HID, NNODE, 0);
        gemm_small_kernel<HID, OUTC><<<NNODE / 8, blk>>>(h2P, W1_ls, nullptr, nullptr, 0, g2P + 64, HID, NNODE, 0);
    }
    // 8. s2 = scatter(w * g2[src] -> dst)
    scatter_kernel<<<(NEDGE * 32) / 256, 256>>>(src, dst, dinvP, g2P, s2P);
    // 9. mu / logstd
    {
        dim3 blk(OUTC / 4, 8);
        gemm_small_kernel<HID, OUTC><<<NNODE / 8, blk>>>(h2P, W0_mu, b_mu, s2P,      HID, out,                 OUTC, NNODE, 0);
        gemm_small_kernel<HID, OUTC><<<NNODE / 8, blk>>>(h2P, W0_ls, b_ls, s2P + 64, HID, out + NNODE * OUTC, OUTC, NNODE, 0);
    }
}

// round 6
// speedup vs baseline: 1.9317x; 1.9317x over previous
#include <cuda_runtime.h>
#include <cstdint>

#define NNODE 10000
#define INC   256
#define HID   128      // 2*OUT_C
#define OUTC  64
#define NEDGE 640000

// ---- big GEMM tiling (mma.sync tf32) ----
#define BM 80
#define BK 16
#define NKT (NNODE / BK)          // 625
#define NSTAGE 4
#define A_BYTES (BM * BK * 4)     // 5120
#define B_BYTES (INC * BK * 4)    // 16384
#define STAGE_BYTES (A_BYTES + B_BYTES)     // 21504
#define GSMEM_TOTAL (NSTAGE * STAGE_BYTES)  // 86016

// ---------------- scratch (device globals; no allocations allowed) ----------
__device__ float g_h  [NNODE * INC];   // relu(x@Wt+bt)
__device__ float g_WtT[INC * NNODE];   // Wt transposed (K-major), tf32-rounded
__device__ float g_g1 [NNODE * HID];   // h @ W1_1
__device__ float g_s1 [NNODE * HID];   // scatter of w*g1[src]
__device__ float g_h2 [NNODE * HID];   // relu(h@W0_1 + s1 + b1)
__device__ float g_g2 [NNODE * HID];   // [h2@W1_mu | h2@W1_ls]
__device__ float g_s2 [NNODE * HID];   // scatter of w*g2[src]
__device__ float g_dinv[NNODE];
__device__ int   g_deg [NNODE];

// ======================= helpers ============================================
__device__ __forceinline__ uint32_t smem_u32(const void* p) {
    uint32_t a;
    asm("{ .reg .u64 t; cvta.to.shared.u64 t, %1; cvt.u32.u64 %0, t; }" : "=r"(a) : "l"(p));
    return a;
}
__device__ __forceinline__ float to_tf32(float x) {
    float y; asm("cvt.rna.tf32.f32 %0, %1;" : "=f"(y) : "f"(x)); return y;
}
__device__ __forceinline__ void cp_async16(uint32_t dst, const void* src) {
    asm volatile("cp.async.cg.shared.global [%0], [%1], 16;" :: "r"(dst), "l"(src));
}
#define CP_COMMIT() asm volatile("cp.async.commit_group;" ::: "memory")
#define CP_WAIT2()  asm volatile("cp.async.wait_group 2;" ::: "memory")

__device__ __forceinline__ void ldsm4(uint32_t& r0, uint32_t& r1, uint32_t& r2, uint32_t& r3,
                                      uint32_t addr) {
    asm volatile("ldmatrix.sync.aligned.m8n8.x4.shared.b16 {%0,%1,%2,%3}, [%4];"
                 : "=r"(r0), "=r"(r1), "=r"(r2), "=r"(r3) : "r"(addr));
}
__device__ __forceinline__ void mma_tf32(float* c, uint32_t a0, uint32_t a1, uint32_t a2,
                                         uint32_t a3, uint32_t b0, uint32_t b1) {
    asm volatile("mma.sync.aligned.m16n8k8.row.col.f32.tf32.tf32.f32 "
                 "{%0,%1,%2,%3}, {%4,%5,%6,%7}, {%8,%9}, {%0,%1,%2,%3};"
                 : "+f"(c[0]), "+f"(c[1]), "+f"(c[2]), "+f"(c[3])
                 : "r"(a0), "r"(a1), "r"(a2), "r"(a3), "r"(b0), "r"(b1));
}

// ---------------- init / degree / dinv --------------------------------------
__global__ void zero_kernel(float* s1, float* s2, int* deg) {
    int i = blockIdx.x * blockDim.x + threadIdx.x;
    if (i < NNODE * HID) { s1[i] = 0.f; s2[i] = 0.f; }
    if (i < NNODE) deg[i] = 0;
}
__global__ void deg_kernel(const int* __restrict__ src, int* __restrict__ deg) {
    int e = blockIdx.x * blockDim.x + threadIdx.x;
    if (e < NEDGE) atomicAdd(&deg[src[e]], 1);
}
__global__ void dinv_kernel(const int* __restrict__ deg, float* __restrict__ dinv) {
    int i = blockIdx.x * blockDim.x + threadIdx.x;
    if (i < NNODE) {
        int d = deg[i];
        dinv[i] = (d > 0) ? rsqrtf((float)d) : 0.f;
    }
}

// ---------------- Wt transpose (+ tf32 rna round) ---------------------------
__global__ void transpose_wt_kernel(const float* __restrict__ Wt, float* __restrict__ WtT) {
    __shared__ float t[32][33];
    int kb = blockIdx.x * 32, nb = blockIdx.y * 32;
    int x = threadIdx.x, y = threadIdx.y;     // block (32, 8)
#pragma unroll
    for (int j = 0; j < 32; j += 8) {
        int k = kb + y + j;
        t[y + j][x] = (k < NNODE) ? to_tf32(Wt[(size_t)k * INC + nb + x]) : 0.f;
    }
    __syncthreads();
#pragma unroll
    for (int j = 0; j < 32; j += 8) {
        int k = kb + x;
        int n = nb + y + j;
        if (k < NNODE) WtT[(size_t)n * NNODE + k] = t[x][y + j];
    }
}

// ---------------- big GEMM: h = relu(x @ Wt + bt) via mma.sync tf32 ---------
// A [10000,10000] row-major; BT = WtT [256,10000] (n-major rows of k, rna-rounded).
// CTA: 128 threads (4 warps), tile 80(M) x 256(N); warp tile 80 x 64.
// smem per stage: A 80x16 f32 (chunk-swizzled rows of 64B), B 256x16 f32 (same).
// swizzle: 16B chunk index c (0..3) stored at c ^ ((row>>1)&3).
extern __shared__ char g_dyn_smem[];

__global__ __launch_bounds__(128) void gemm_big_mma(
    const float* __restrict__ A, const float* __restrict__ BT,
    const float* __restrict__ bias, float* __restrict__ C)
{
    char* smem = g_dyn_smem;
    const uint32_t sbase = smem_u32(smem);
    const int tid  = threadIdx.x;
    const int lane = tid & 31;
    const int w    = tid >> 5;
    const int row0 = blockIdx.x * BM;

    float c[5][8][4];
#pragma unroll
    for (int i = 0; i < 5; i++)
#pragma unroll
        for (int j = 0; j < 8; j++)
#pragma unroll
            for (int q = 0; q < 4; q++) c[i][j][q] = 0.f;

    // ---- A register staging: 320 chunks (16B), thread handles i = tid + 128*it ----
    float4 ra[3];

    auto ldgA = [&](int k0) {
#pragma unroll
        for (int it = 0; it < 3; it++) {
            int i = tid + it * 128;
            if (i < 320) {
                int r  = i >> 2;
                int kc = i & 3;
                ra[it] = *(const float4*)(A + (size_t)(row0 + r) * NNODE + k0 + kc * 4);
            }
        }
    };
    auto stsA = [&](int stage) {
        char* base = smem + stage * STAGE_BYTES;
#pragma unroll
        for (int it = 0; it < 3; it++) {
            int i = tid + it * 128;
            if (i < 320) {
                int r  = i >> 2;
                int kc = i & 3;
                float4 v = ra[it];
                v.x = to_tf32(v.x); v.y = to_tf32(v.y); v.z = to_tf32(v.z); v.w = to_tf32(v.w);
                int chunk = r * 4 + (kc ^ ((r >> 1) & 3));
                *(float4*)(base + chunk * 16) = v;
            }
        }
    };
    // ---- B cp.async staging: 1024 chunks ----
    auto cpB = [&](int stage, int k0) {
        uint32_t base = sbase + stage * STAGE_BYTES + A_BYTES;
#pragma unroll
        for (int it = 0; it < 8; it++) {
            int i  = tid + it * 128;
            int n  = i >> 2;
            int kc = i & 3;
            uint32_t dst = base + (uint32_t)(n * 4 + (kc ^ ((n >> 1) & 3))) * 16;
            cp_async16(dst, BT + (size_t)n * NNODE + k0 + kc * 4);
        }
    };

    // ---- ldmatrix address components ----
    // A: matrices m0..m3 of x4: rows (lane&7)+8*((lane>>3)&1), chunk ks*2 + ((lane>>4)&1)
    const int a_rl   = (lane & 7) + ((lane >> 3) & 1) * 8;
    const int a_cbit = (lane >> 4) & 1;
    // B: n = w*64 + (nf + ((lane>>4)&1))*8 + (lane&7); chunk ks*2 + ((lane>>3)&1)
    const int b_noff = ((lane >> 4) & 1) * 8 + (lane & 7) + w * 64;
    const int b_cbit = (lane >> 3) & 1;

    // ---- prologue ----
    cpB(0, 0);  CP_COMMIT();
    cpB(1, 16); CP_COMMIT();
    cpB(2, 32); CP_COMMIT();
    ldgA(0);        stsA(0);
    ldgA(1 * BK);   stsA(1);
    ldgA(2 * BK);   stsA(2);
    ldgA(3 * BK);   // tile 3 held in regs

    for (int kt = 0; kt < NKT; kt++) {
        CP_WAIT2();
        __syncthreads();

        const int kn = kt + 3;
        if (kn < NKT) {
            cpB(kn & 3, kn * BK);
            stsA(kn & 3);
        }
        CP_COMMIT();                       // may be empty near the tail
        if (kt + 4 < NKT) ldgA((kt + 4) * BK);

        // ---- compute stage kt&3 ----
        const uint32_t abase = sbase + (uint32_t)(kt & 3) * STAGE_BYTES;
        const uint32_t bbase = abase + A_BYTES;
#pragma unroll
        for (int ks = 0; ks < 2; ks++) {
            uint32_t bb[4][4];
#pragma unroll
            for (int np = 0; np < 4; np++) {
                int n = b_noff + np * 16;                  // nf = 2*np
                int ccol = (ks * 2 + b_cbit) ^ ((n >> 1) & 3);
                ldsm4(bb[np][0], bb[np][1], bb[np][2], bb[np][3],
                      bbase + (uint32_t)(n * 4 + ccol) * 16);
            }
#pragma unroll
            for (int mf = 0; mf < 5; mf++) {
                int r = mf * 16 + a_rl;
                int ccol = (ks * 2 + a_cbit) ^ ((r >> 1) & 3);
                uint32_t a0, a1, a2, a3;
                ldsm4(a0, a1, a2, a3, abase + (uint32_t)(r * 4 + ccol) * 16);
#pragma unroll
                for (int np = 0; np < 4; np++) {
                    mma_tf32(c[mf][np * 2],     a0, a1, a2, a3, bb[np][0], bb[np][1]);
                    mma_tf32(c[mf][np * 2 + 1], a0, a1, a2, a3, bb[np][2], bb[np][3]);
                }
            }
        }
    }

    // ---- epilogue: bias + relu ----
    const int g = lane >> 2;            // row within 8
    const int t2 = (lane & 3) * 2;      // col pair
#pragma unroll
    for (int mf = 0; mf < 5; mf++) {
        int r = row0 + mf * 16 + g;
#pragma unroll
        for (int nf = 0; nf < 8; nf++) {
            int col = w * 64 + nf * 8 + t2;
            float2 bb = *(const float2*)(bias + col);
            float2 o0, o1;
            o0.x = fmaxf(c[mf][nf][0] + bb.x, 0.f);
            o0.y = fmaxf(c[mf][nf][1] + bb.y, 0.f);
            o1.x = fmaxf(c[mf][nf][2] + bb.x, 0.f);
            o1.y = fmaxf(c[mf][nf][3] + bb.y, 0.f);
            *(float2*)(C + (size_t)r * INC + col)       = o0;
            *(float2*)(C + (size_t)(r + 8) * INC + col) = o1;
        }
    }
}

// ---------------- small GEMM with fused epilogue ----------------------------
template<int K, int NC>
__global__ void gemm_small_kernel(
    const float* __restrict__ A, const float* __restrict__ B,
    const float* __restrict__ bias, const float* __restrict__ addend,
    int ld_add, float* __restrict__ C, int ldc, int M, int do_relu)
{
    __shared__ float sA[8][K];
    const int tx = threadIdx.x;
    const int ty = threadIdx.y;
    const int nt = (NC / 4) * 8;
    const int tid = ty * (NC / 4) + tx;
    const int row0 = blockIdx.x * 8;

    const float4* A4 = (const float4*)A;
    const int nf4 = 8 * K / 4;
    for (int i = tid; i < nf4; i += nt) {
        int r = i / (K / 4);
        int col = i - r * (K / 4);
        int gr = row0 + r;
        float4 v = make_float4(0.f,0.f,0.f,0.f);
        if (gr < M) v = A4[gr * (K / 4) + col];
        ((float4*)&sA[r][0])[col] = v;
    }
    __syncthreads();

    const float4* B4 = (const float4*)B;
    float4 acc = make_float4(0.f,0.f,0.f,0.f);
#pragma unroll 8
    for (int k = 0; k < K; k++) {
        float a = sA[ty][k];
        float4 b = __ldg(&B4[k * (NC / 4) + tx]);
        acc.x += a * b.x; acc.y += a * b.y; acc.z += a * b.z; acc.w += a * b.w;
    }

    int r = row0 + ty;
    if (r < M) {
        if (addend) {
            float4 ad = *(const float4*)(addend + (size_t)r * ld_add + tx * 4);
            acc.x += ad.x; acc.y += ad.y; acc.z += ad.z; acc.w += ad.w;
        }
        if (bias) {
            float4 bb = ((const float4*)bias)[tx];
            acc.x += bb.x; acc.y += bb.y; acc.z += bb.z; acc.w += bb.w;
        }
        if (do_relu) {
            acc.x = fmaxf(acc.x, 0.f); acc.y = fmaxf(acc.y, 0.f);
            acc.z = fmaxf(acc.z, 0.f); acc.w = fmaxf(acc.w, 0.f);
        }
        *(float4*)(C + (size_t)r * ldc + tx * 4) = acc;
    }
}

// ---------------- edge scatter: S[dst] += (-dinv[src]*dinv[dst]) * G[src] ---
__global__ void scatter_kernel(
    const int* __restrict__ src, const int* __restrict__ dst,
    const float* __restrict__ dinv, const float* __restrict__ G,
    float* __restrict__ S)
{
    int t = blockIdx.x * blockDim.x + threadIdx.x;
    int e = t >> 5;
    int lane = t & 31;
    if (e >= NEDGE) return;
    int s = src[e], d = dst[e];
    float w = -dinv[s] * dinv[d];
    const float4* G4 = (const float4*)G;
    float4 v = __ldg(&G4[s * 32 + lane]);
    float* p = &S[d * HID + lane * 4];
    atomicAdd(p + 0, v.x * w);
    atomicAdd(p + 1, v.y * w);
    atomicAdd(p + 2, v.z * w);
    atomicAdd(p + 3, v.w * w);
}

// ---------------- launch -----------------------------------------------------
extern "C" void kernel_launch(void* const* d_in, const int* in_sizes, int n_in,
                              void* d_out, int out_size)
{
    const float* x     = (const float*)d_in[0];
    const int*   ei    = (const int*)  d_in[1];
    const float* Wt    = (const float*)d_in[2];
    const float* bt    = (const float*)d_in[3];
    const float* W0_1  = (const float*)d_in[4];
    const float* W1_1  = (const float*)d_in[5];
    const float* b1    = (const float*)d_in[6];
    const float* W0_mu = (const float*)d_in[7];
    const float* W1_mu = (const float*)d_in[8];
    const float* b_mu  = (const float*)d_in[9];
    const float* W0_ls = (const float*)d_in[10];
    const float* W1_ls = (const float*)d_in[11];
    const float* b_ls  = (const float*)d_in[12];
    float* out = (float*)d_out;

    const int* src = ei;
    const int* dst = ei + NEDGE;

    float *hP, *wttP, *g1P, *s1P, *h2P, *g2P, *s2P, *dinvP;
    int* degP;
    cudaGetSymbolAddress((void**)&hP,    g_h);
    cudaGetSymbolAddress((void**)&wttP,  g_WtT);
    cudaGetSymbolAddress((void**)&g1P,   g_g1);
    cudaGetSymbolAddress((void**)&s1P,   g_s1);
    cudaGetSymbolAddress((void**)&h2P,   g_h2);
    cudaGetSymbolAddress((void**)&g2P,   g_g2);
    cudaGetSymbolAddress((void**)&s2P,   g_s2);
    cudaGetSymbolAddress((void**)&dinvP, g_dinv);
    cudaGetSymbolAddress((void**)&degP,  g_deg);

    // 1. zero scratch + degree accumulators
    zero_kernel<<<(NNODE * HID + 255) / 256, 256>>>(s1P, s2P, degP);
    // 2. degrees + dinv
    deg_kernel<<<(NEDGE + 255) / 256, 256>>>(src, degP);
    dinv_kernel<<<(NNODE + 255) / 256, 256>>>(degP, dinvP);
    // 3a. transpose Wt (K-major, tf32-rounded)
    {
        dim3 grid((NNODE + 31) / 32, INC / 32);
        transpose_wt_kernel<<<grid, dim3(32, 8)>>>(Wt, wttP);
    }
    // 3b. h = relu(x @ Wt + bt) via mma.sync tf32
    {
        cudaFuncSetAttribute(gemm_big_mma,
                             cudaFuncAttributeMaxDynamicSharedMemorySize, GSMEM_TOTAL);
        gemm_big_mma<<<NNODE / BM, 128, GSMEM_TOTAL>>>(x, wttP, bt, hP);
    }
    // 4. g1 = h @ W1_1
    {
        dim3 blk(HID / 4, 8);
        gemm_small_kernel<INC, HID><<<NNODE / 8, blk>>>(hP, W1_1, nullptr, nullptr, 0, g1P, HID, NNODE, 0);
    }
    // 5. s1 = scatter(w * g1[src] -> dst)
    scatter_kernel<<<(NEDGE * 32) / 256, 256>>>(src, dst, dinvP, g1P, s1P);
    // 6. h2 = relu(h @ W0_1 + s1 + b1)
    {
        dim3 blk(HID / 4, 8);
        gemm_small_kernel<INC, HID><<<NNODE / 8, blk>>>(hP, W0_1, b1, s1P, HID, h2P, HID, NNODE, 1);
    }
    // 7. g2 = [h2 @ W1_mu | h2 @ W1_ls]
    {
        dim3 blk(OUTC / 4, 8);
        gemm_small_kernel<HID, OUTC><<<NNODE / 8, blk>>>(h2P, W1_mu, nullptr, nullptr, 0, g2P,      HID, NNODE, 0);
        gemm_small_kernel<HID, OUTC><<<NNODE / 8, blk>>>(h2P, W1_ls, nullptr, nullptr, 0, g2P + 64, HID, NNODE, 0);
    }
    // 8. s2 = scatter(w * g2[src] -> dst)
    scatter_kernel<<<(NEDGE * 32) / 256, 256>>>(src, dst, dinvP, g2P, s2P);
    // 9. mu / logstd
    {
        dim3 blk(OUTC / 4, 8);
        gemm_small_kernel<HID, OUTC><<<NNODE / 8, blk>>>(h2P, W0_mu, b_mu, s2P,      HID, out,                 OUTC, NNODE, 0);
        gemm_small_kernel<HID, OUTC><<<NNODE / 8, blk>>>(h2P, W0_ls, b_ls, s2P + 64, HID, out + NNODE * OUTC, OUTC, NNODE, 0);
    }
}

// round 7
// speedup vs baseline: 2.5628x; 1.3267x over previous
#include <cuda_runtime.h>
#include <cstdint>

#define NNODE 10000
#define INC   256
#define HID   128      // 2*OUT_C
#define OUTC  64
#define NEDGE 640000

// ---- big GEMM tiling (mma.sync tf32) ----
#define BM 80
#define BK 16
#define NKT (NNODE / BK)          // 625
#define NSTAGE 4
#define A_BYTES (BM * BK * 4)     // 5120
#define B_BYTES (INC * BK * 4)    // 16384
#define STAGE_BYTES (A_BYTES + B_BYTES)     // 21504
#define GSMEM_TOTAL (NSTAGE * STAGE_BYTES)  // 86016

// ---------------- scratch (device globals; no allocations allowed) ----------
__device__ float g_h  [NNODE * INC];   // relu(x@Wt+bt)
__device__ float g_WtT[INC * NNODE];   // Wt transposed (K-major), tf32-rounded
__device__ float g_g1 [NNODE * HID];   // h @ W1_1
__device__ float g_s1 [NNODE * HID];   // gather of w*g1[src]
__device__ float g_h2 [NNODE * HID];   // relu(h@W0_1 + s1 + b1)
__device__ float g_g2 [NNODE * HID];   // [h2@W1_mu | h2@W1_ls]
__device__ float g_s2 [NNODE * HID];   // gather of w*g2[src]
__device__ float g_dinv[NNODE];
__device__ int   g_deg [NNODE];        // out-degree (by src) for dinv
__device__ int   g_dstc[NNODE];        // in-degree (by dst) for CSR
__device__ int   g_off [NNODE + 1];    // CSR offsets (by dst)
__device__ int   g_cur [NNODE];        // fill cursors
__device__ int   g_esrc[NEDGE];        // CSR: src per slot
__device__ float g_ew  [NEDGE];        // CSR: edge weight per slot

// ======================= helpers ============================================
__device__ __forceinline__ uint32_t smem_u32(const void* p) {
    uint32_t a;
    asm("{ .reg .u64 t; cvta.to.shared.u64 t, %1; cvt.u32.u64 %0, t; }" : "=r"(a) : "l"(p));
    return a;
}
__device__ __forceinline__ float to_tf32(float x) {
    float y; asm("cvt.rna.tf32.f32 %0, %1;" : "=f"(y) : "f"(x)); return y;
}
__device__ __forceinline__ void cp_async16(uint32_t dst, const void* src) {
    asm volatile("cp.async.cg.shared.global [%0], [%1], 16;" :: "r"(dst), "l"(src));
}
#define CP_COMMIT() asm volatile("cp.async.commit_group;" ::: "memory")
#define CP_WAIT2()  asm volatile("cp.async.wait_group 2;" ::: "memory")

__device__ __forceinline__ void ldsm4(uint32_t& r0, uint32_t& r1, uint32_t& r2, uint32_t& r3,
                                      uint32_t addr) {
    asm volatile("ldmatrix.sync.aligned.m8n8.x4.shared.b16 {%0,%1,%2,%3}, [%4];"
                 : "=r"(r0), "=r"(r1), "=r"(r2), "=r"(r3) : "r"(addr));
}
__device__ __forceinline__ void mma_tf32(float* c, uint32_t a0, uint32_t a1, uint32_t a2,
                                         uint32_t a3, uint32_t b0, uint32_t b1) {
    asm volatile("mma.sync.aligned.m16n8k8.row.col.f32.tf32.tf32.f32 "
                 "{%0,%1,%2,%3}, {%4,%5,%6,%7}, {%8,%9}, {%0,%1,%2,%3};"
                 : "+f"(c[0]), "+f"(c[1]), "+f"(c[2]), "+f"(c[3])
                 : "r"(a0), "r"(a1), "r"(a2), "r"(a3), "r"(b0), "r"(b1));
}

// ---------------- CSR build --------------------------------------------------
__global__ void zero_cnt_kernel(int* deg, int* dstc) {
    int i = blockIdx.x * blockDim.x + threadIdx.x;
    if (i < NNODE) { deg[i] = 0; dstc[i] = 0; }
}
__global__ void cnt_kernel(const int* __restrict__ src, const int* __restrict__ dst,
                           int* __restrict__ deg, int* __restrict__ dstc) {
    int e = blockIdx.x * blockDim.x + threadIdx.x;
    if (e < NEDGE) {
        atomicAdd(&deg[src[e]], 1);
        atomicAdd(&dstc[dst[e]], 1);
    }
}
__global__ void dinv_kernel(const int* __restrict__ deg, float* __restrict__ dinv) {
    int i = blockIdx.x * blockDim.x + threadIdx.x;
    if (i < NNODE) {
        int d = deg[i];
        dinv[i] = (d > 0) ? rsqrtf((float)d) : 0.f;
    }
}
// single-block exclusive scan over dstc -> off, cursor; off[NNODE] = total
__global__ __launch_bounds__(1024) void scan_kernel(
    const int* __restrict__ cnt, int* __restrict__ off, int* __restrict__ cursor)
{
    __shared__ int s[1024];
    const int tid = threadIdx.x;
    const int CH = (NNODE + 1023) / 1024;   // 10
    int base = tid * CH;
    int local[CH];
    int sum = 0;
#pragma unroll
    for (int j = 0; j < CH; j++) {
        int i = base + j;
        int v = (i < NNODE) ? cnt[i] : 0;
        local[j] = sum;
        sum += v;
    }
    s[tid] = sum;
    __syncthreads();
    for (int d = 1; d < 1024; d <<= 1) {
        int v = (tid >= d) ? s[tid - d] : 0;
        __syncthreads();
        s[tid] += v;
        __syncthreads();
    }
    int pre = (tid == 0) ? 0 : s[tid - 1];
#pragma unroll
    for (int j = 0; j < CH; j++) {
        int i = base + j;
        if (i < NNODE) {
            int o = pre + local[j];
            off[i] = o;
            cursor[i] = o;
        }
    }
    if (tid == 1023) off[NNODE] = s[1023];
}
__global__ void fill_kernel(const int* __restrict__ src, const int* __restrict__ dst,
                            const float* __restrict__ dinv, int* __restrict__ cursor,
                            int* __restrict__ esrc, float* __restrict__ ew) {
    int e = blockIdx.x * blockDim.x + threadIdx.x;
    if (e < NEDGE) {
        int s = src[e], d = dst[e];
        int pos = atomicAdd(&cursor[d], 1);
        esrc[pos] = s;
        ew[pos] = -dinv[s] * dinv[d];
    }
}

// ---------------- gather: S[d] = sum_e w_e * G[src_e], warp per node ---------
__global__ void gather_kernel(const int* __restrict__ off, const int* __restrict__ esrc,
                              const float* __restrict__ ew, const float* __restrict__ G,
                              float* __restrict__ S)
{
    int node = blockIdx.x * 8 + (threadIdx.x >> 5);
    int lane = threadIdx.x & 31;
    if (node >= NNODE) return;
    int beg = off[node], end = off[node + 1];
    const float4* G4 = (const float4*)G;
    float4 acc = make_float4(0.f, 0.f, 0.f, 0.f);
    for (int base = beg; base < end; base += 32) {
        int idx = base + lane;
        int   se = 0;
        float we = 0.f;
        if (idx < end) { se = __ldg(&esrc[idx]); we = __ldg(&ew[idx]); }
        int n = min(32, end - base);
        for (int j = 0; j < n; j++) {
            int   sj = __shfl_sync(0xffffffffu, se, j);
            float wj = __shfl_sync(0xffffffffu, we, j);
            float4 v = __ldg(&G4[sj * 32 + lane]);
            acc.x += wj * v.x; acc.y += wj * v.y;
            acc.z += wj * v.z; acc.w += wj * v.w;
        }
    }
    ((float4*)S)[node * 32 + lane] = acc;
}

// ---------------- Wt transpose (+ tf32 rna round) ---------------------------
__global__ void transpose_wt_kernel(const float* __restrict__ Wt, float* __restrict__ WtT) {
    __shared__ float t[32][33];
    int kb = blockIdx.x * 32, nb = blockIdx.y * 32;
    int x = threadIdx.x, y = threadIdx.y;     // block (32, 8)
#pragma unroll
    for (int j = 0; j < 32; j += 8) {
        int k = kb + y + j;
        t[y + j][x] = (k < NNODE) ? to_tf32(Wt[(size_t)k * INC + nb + x]) : 0.f;
    }
    __syncthreads();
#pragma unroll
    for (int j = 0; j < 32; j += 8) {
        int k = kb + x;
        int n = nb + y + j;
        if (k < NNODE) WtT[(size_t)n * NNODE + k] = t[x][y + j];
    }
}

// ---------------- big GEMM: h = relu(x @ Wt + bt) via mma.sync tf32 ---------
extern __shared__ char g_dyn_smem[];

__global__ __launch_bounds__(128) void gemm_big_mma(
    const float* __restrict__ A, const float* __restrict__ BT,
    const float* __restrict__ bias, float* __restrict__ C)
{
    char* smem = g_dyn_smem;
    const uint32_t sbase = smem_u32(smem);
    const int tid  = threadIdx.x;
    const int lane = tid & 31;
    const int w    = tid >> 5;
    const int row0 = blockIdx.x * BM;

    float c[5][8][4];
#pragma unroll
    for (int i = 0; i < 5; i++)
#pragma unroll
        for (int j = 0; j < 8; j++)
#pragma unroll
            for (int q = 0; q < 4; q++) c[i][j][q] = 0.f;

    float4 ra[3];

    auto ldgA = [&](int k0) {
#pragma unroll
        for (int it = 0; it < 3; it++) {
            int i = tid + it * 128;
            if (i < 320) {
                int r  = i >> 2;
                int kc = i & 3;
                ra[it] = *(const float4*)(A + (size_t)(row0 + r) * NNODE + k0 + kc * 4);
            }
        }
    };
    auto stsA = [&](int stage) {
        char* base = smem + stage * STAGE_BYTES;
#pragma unroll
        for (int it = 0; it < 3; it++) {
            int i = tid + it * 128;
            if (i < 320) {
                int r  = i >> 2;
                int kc = i & 3;
                float4 v = ra[it];
                v.x = to_tf32(v.x); v.y = to_tf32(v.y); v.z = to_tf32(v.z); v.w = to_tf32(v.w);
                int chunk = r * 4 + (kc ^ ((r >> 1) & 3));
                *(float4*)(base + chunk * 16) = v;
            }
        }
    };
    auto cpB = [&](int stage, int k0) {
        uint32_t base = sbase + stage * STAGE_BYTES + A_BYTES;
#pragma unroll
        for (int it = 0; it < 8; it++) {
            int i  = tid + it * 128;
            int n  = i >> 2;
            int kc = i & 3;
            uint32_t dst = base + (uint32_t)(n * 4 + (kc ^ ((n >> 1) & 3))) * 16;
            cp_async16(dst, BT + (size_t)n * NNODE + k0 + kc * 4);
        }
    };

    const int a_rl   = (lane & 7) + ((lane >> 3) & 1) * 8;
    const int a_cbit = (lane >> 4) & 1;
    const int b_noff = ((lane >> 4) & 1) * 8 + (lane & 7) + w * 64;
    const int b_cbit = (lane >> 3) & 1;

    cpB(0, 0);  CP_COMMIT();
    cpB(1, 16); CP_COMMIT();
    cpB(2, 32); CP_COMMIT();
    ldgA(0);        stsA(0);
    ldgA(1 * BK);   stsA(1);
    ldgA(2 * BK);   stsA(2);
    ldgA(3 * BK);

    for (int kt = 0; kt < NKT; kt++) {
        CP_WAIT2();
        __syncthreads();

        const int kn = kt + 3;
        if (kn < NKT) {
            cpB(kn & 3, kn * BK);
            stsA(kn & 3);
        }
        CP_COMMIT();
        if (kt + 4 < NKT) ldgA((kt + 4) * BK);

        const uint32_t abase = sbase + (uint32_t)(kt & 3) * STAGE_BYTES;
        const uint32_t bbase = abase + A_BYTES;
#pragma unroll
        for (int ks = 0; ks < 2; ks++) {
            uint32_t bb[4][4];
#pragma unroll
            for (int np = 0; np < 4; np++) {
                int n = b_noff + np * 16;
                int ccol = (ks * 2 + b_cbit) ^ ((n >> 1) & 3);
                ldsm4(bb[np][0], bb[np][1], bb[np][2], bb[np][3],
                      bbase + (uint32_t)(n * 4 + ccol) * 16);
            }
#pragma unroll
            for (int mf = 0; mf < 5; mf++) {
                int r = mf * 16 + a_rl;
                int ccol = (ks * 2 + a_cbit) ^ ((r >> 1) & 3);
                uint32_t a0, a1, a2, a3;
                ldsm4(a0, a1, a2, a3, abase + (uint32_t)(r * 4 + ccol) * 16);
#pragma unroll
                for (int np = 0; np < 4; np++) {
                    mma_tf32(c[mf][np * 2],     a0, a1, a2, a3, bb[np][0], bb[np][1]);
                    mma_tf32(c[mf][np * 2 + 1], a0, a1, a2, a3, bb[np][2], bb[np][3]);
                }
            }
        }
    }

    const int g = lane >> 2;
    const int t2 = (lane & 3) * 2;
#pragma unroll
    for (int mf = 0; mf < 5; mf++) {
        int r = row0 + mf * 16 + g;
#pragma unroll
        for (int nf = 0; nf < 8; nf++) {
            int col = w * 64 + nf * 8 + t2;
            float2 bb = *(const float2*)(bias + col);
            float2 o0, o1;
            o0.x = fmaxf(c[mf][nf][0] + bb.x, 0.f);
            o0.y = fmaxf(c[mf][nf][1] + bb.y, 0.f);
            o1.x = fmaxf(c[mf][nf][2] + bb.x, 0.f);
            o1.y = fmaxf(c[mf][nf][3] + bb.y, 0.f);
            *(float2*)(C + (size_t)r * INC + col)       = o0;
            *(float2*)(C + (size_t)(r + 8) * INC + col) = o1;
        }
    }
}

// ---------------- small GEMM with fused epilogue ----------------------------
template<int K, int NC>
__global__ void gemm_small_kernel(
    const float* __restrict__ A, const float* __restrict__ B,
    const float* __restrict__ bias, const float* __restrict__ addend,
    int ld_add, float* __restrict__ C, int ldc, int M, int do_relu)
{
    __shared__ float sA[8][K];
    const int tx = threadIdx.x;
    const int ty = threadIdx.y;
    const int nt = (NC / 4) * 8;
    const int tid = ty * (NC / 4) + tx;
    const int row0 = blockIdx.x * 8;

    const float4* A4 = (const float4*)A;
    const int nf4 = 8 * K / 4;
    for (int i = tid; i < nf4; i += nt) {
        int r = i / (K / 4);
        int col = i - r * (K / 4);
        int gr = row0 + r;
        float4 v = make_float4(0.f,0.f,0.f,0.f);
        if (gr < M) v = A4[gr * (K / 4) + col];
        ((float4*)&sA[r][0])[col] = v;
    }
    __syncthreads();

    const float4* B4 = (const float4*)B;
    float4 acc = make_float4(0.f,0.f,0.f,0.f);
#pragma unroll 8
    for (int k = 0; k < K; k++) {
        float a = sA[ty][k];
        float4 b = __ldg(&B4[k * (NC / 4) + tx]);
        acc.x += a * b.x; acc.y += a * b.y; acc.z += a * b.z; acc.w += a * b.w;
    }

    int r = row0 + ty;
    if (r < M) {
        if (addend) {
            float4 ad = *(const float4*)(addend + (size_t)r * ld_add + tx * 4);
            acc.x += ad.x; acc.y += ad.y; acc.z += ad.z; acc.w += ad.w;
        }
        if (bias) {
            float4 bb = ((const float4*)bias)[tx];
            acc.x += bb.x; acc.y += bb.y; acc.z += bb.z; acc.w += bb.w;
        }
        if (do_relu) {
            acc.x = fmaxf(acc.x, 0.f); acc.y = fmaxf(acc.y, 0.f);
            acc.z = fmaxf(acc.z, 0.f); acc.w = fmaxf(acc.w, 0.f);
        }
        *(float4*)(C + (size_t)r * ldc + tx * 4) = acc;
    }
}

// ---------------- launch -----------------------------------------------------
extern "C" void kernel_launch(void* const* d_in, const int* in_sizes, int n_in,
                              void* d_out, int out_size)
{
    const float* x     = (const float*)d_in[0];
    const int*   ei    = (const int*)  d_in[1];
    const float* Wt    = (const float*)d_in[2];
    const float* bt    = (const float*)d_in[3];
    const float* W0_1  = (const float*)d_in[4];
    const float* W1_1  = (const float*)d_in[5];
    const float* b1    = (const float*)d_in[6];
    const float* W0_mu = (const float*)d_in[7];
    const float* W1_mu = (const float*)d_in[8];
    const float* b_mu  = (const float*)d_in[9];
    const float* W0_ls = (const float*)d_in[10];
    const float* W1_ls = (const float*)d_in[11];
    const float* b_ls  = (const float*)d_in[12];
    float* out = (float*)d_out;

    const int* src = ei;
    const int* dst = ei + NEDGE;

    float *hP, *wttP, *g1P, *s1P, *h2P, *g2P, *s2P, *dinvP, *ewP;
    int *degP, *dstcP, *offP, *curP, *esrcP;
    cudaGetSymbolAddress((void**)&hP,    g_h);
    cudaGetSymbolAddress((void**)&wttP,  g_WtT);
    cudaGetSymbolAddress((void**)&g1P,   g_g1);
    cudaGetSymbolAddress((void**)&s1P,   g_s1);
    cudaGetSymbolAddress((void**)&h2P,   g_h2);
    cudaGetSymbolAddress((void**)&g2P,   g_g2);
    cudaGetSymbolAddress((void**)&s2P,   g_s2);
    cudaGetSymbolAddress((void**)&dinvP, g_dinv);
    cudaGetSymbolAddress((void**)&degP,  g_deg);
    cudaGetSymbolAddress((void**)&dstcP, g_dstc);
    cudaGetSymbolAddress((void**)&offP,  g_off);
    cudaGetSymbolAddress((void**)&curP,  g_cur);
    cudaGetSymbolAddress((void**)&esrcP, g_esrc);
    cudaGetSymbolAddress((void**)&ewP,   g_ew);

    // --- CSR build (by dst) + dinv ---
    zero_cnt_kernel<<<(NNODE + 255) / 256, 256>>>(degP, dstcP);
    cnt_kernel<<<(NEDGE + 255) / 256, 256>>>(src, dst, degP, dstcP);
    dinv_kernel<<<(NNODE + 255) / 256, 256>>>(degP, dinvP);
    scan_kernel<<<1, 1024>>>(dstcP, offP, curP);
    fill_kernel<<<(NEDGE + 255) / 256, 256>>>(src, dst, dinvP, curP, esrcP, ewP);

    // --- transpose Wt (K-major, tf32-rounded) ---
    {
        dim3 grid((NNODE + 31) / 32, INC / 32);
        transpose_wt_kernel<<<grid, dim3(32, 8)>>>(Wt, wttP);
    }
    // --- h = relu(x @ Wt + bt) via mma.sync tf32 ---
    {
        cudaFuncSetAttribute(gemm_big_mma,
                             cudaFuncAttributeMaxDynamicSharedMemorySize, GSMEM_TOTAL);
        gemm_big_mma<<<NNODE / BM, 128, GSMEM_TOTAL>>>(x, wttP, bt, hP);
    }
    // --- g1 = h @ W1_1 ---
    {
        dim3 blk(HID / 4, 8);
        gemm_small_kernel<INC, HID><<<NNODE / 8, blk>>>(hP, W1_1, nullptr, nullptr, 0, g1P, HID, NNODE, 0);
    }
    // --- s1 = gather(w * g1[src]) ---
    gather_kernel<<<(NNODE + 7) / 8, 256>>>(offP, esrcP, ewP, g1P, s1P);
    // --- h2 = relu(h @ W0_1 + s1 + b1) ---
    {
        dim3 blk(HID / 4, 8);
        gemm_small_kernel<INC, HID><<<NNODE / 8, blk>>>(hP, W0_1, b1, s1P, HID, h2P, HID, NNODE, 1);
    }
    // --- g2 = [h2 @ W1_mu | h2 @ W1_ls] ---
    {
        dim3 blk(OUTC / 4, 8);
        gemm_small_kernel<HID, OUTC><<<NNODE / 8, blk>>>(h2P, W1_mu, nullptr, nullptr, 0, g2P,      HID, NNODE, 0);
        gemm_small_kernel<HID, OUTC><<<NNODE / 8, blk>>>(h2P, W1_ls, nullptr, nullptr, 0, g2P + 64, HID, NNODE, 0);
    }
    // --- s2 = gather(w * g2[src]) ---
    gather_kernel<<<(NNODE + 7) / 8, 256>>>(offP, esrcP, ewP, g2P, s2P);
    // --- mu / logstd ---
    {
        dim3 blk(OUTC / 4, 8);
        gemm_small_kernel<HID, OUTC><<<NNODE / 8, blk>>>(h2P, W0_mu, b_mu, s2P,      HID, out,                 OUTC, NNODE, 0);
        gemm_small_kernel<HID, OUTC><<<NNODE / 8, blk>>>(h2P, W0_ls, b_ls, s2P + 64, HID, out + NNODE * OUTC, OUTC, NNODE, 0);
    }
}

// round 9
// speedup vs baseline: 2.6950x; 1.0516x over previous
#include <cuda_runtime.h>
#include <cuda_fp16.h>
#include <cstdint>

#define NNODE 10000
#define INC   256
#define HID   128      // 2*OUT_C
#define OUTC  64
#define NEDGE 640000

// ---- big GEMM tiling (mma.sync fp16, m16n8k16) ----
#define BM 80
#define BK 16
#define NKT (NNODE / BK)          // 625
#define A_BYTES (BM * BK * 2)     // 2560 (fp16)
#define B_BYTES (INC * BK * 2)    // 8192 (fp16)
#define STAGE_BYTES (A_BYTES + B_BYTES)     // 10752
#define NSTAGE 4
#define GSMEM_TOTAL (NSTAGE * STAGE_BYTES)  // 43008

// ---------------- scratch (device globals; no allocations allowed) ----------
__device__ float  g_h  [NNODE * INC];   // relu(x@Wt+bt)  (f32)
__device__ __half g_WtT[INC * NNODE];   // Wt transposed (K-major), fp16
__device__ float  g_g1 [NNODE * HID];   // h @ W1_1
__device__ float  g_hw [NNODE * HID];   // h @ W0_1
__device__ float  g_s1 [NNODE * HID];   // gather of w*g1[src]
__device__ float  g_h2 [NNODE * HID];   // relu(hw + s1 + b1)
__device__ float  g_g2 [NNODE * HID];   // [h2@W1_mu | h2@W1_ls]
__device__ float  g_hw2[NNODE * HID];   // [h2@W0_mu | h2@W0_ls]
__device__ float  g_s2 [NNODE * HID];   // gather of w*g2[src]
__device__ float  g_dinv[NNODE];
__device__ int    g_deg [NNODE];        // out-degree (by src) for dinv
__device__ int    g_dstc[NNODE];        // in-degree (by dst) for CSR
__device__ int    g_off [NNODE + 1];    // CSR offsets (by dst)
__device__ int    g_cur [NNODE];        // fill cursors
__device__ int    g_esrc[NEDGE];        // CSR: src per slot
__device__ float  g_ew  [NEDGE];        // CSR: edge weight per slot

// ======================= helpers ============================================
__device__ __forceinline__ uint32_t smem_u32(const void* p) {
    uint32_t a;
    asm("{ .reg .u64 t; cvta.to.shared.u64 t, %1; cvt.u32.u64 %0, t; }" : "=r"(a) : "l"(p));
    return a;
}
__device__ __forceinline__ void cp_async16(uint32_t dst, const void* src) {
    asm volatile("cp.async.cg.shared.global [%0], [%1], 16;" :: "r"(dst), "l"(src));
}
#define CP_COMMIT() asm volatile("cp.async.commit_group;" ::: "memory")
#define CP_WAIT2()  asm volatile("cp.async.wait_group 2;" ::: "memory")

__device__ __forceinline__ void ldsm4(uint32_t& r0, uint32_t& r1, uint32_t& r2, uint32_t& r3,
                                      uint32_t addr) {
    asm volatile("ldmatrix.sync.aligned.m8n8.x4.shared.b16 {%0,%1,%2,%3}, [%4];"
                 : "=r"(r0), "=r"(r1), "=r"(r2), "=r"(r3) : "r"(addr));
}
__device__ __forceinline__ void mma_f16(float* c, uint32_t a0, uint32_t a1, uint32_t a2,
                                        uint32_t a3, uint32_t b0, uint32_t b1) {
    asm volatile("mma.sync.aligned.m16n8k16.row.col.f32.f16.f16.f32 "
                 "{%0,%1,%2,%3}, {%4,%5,%6,%7}, {%8,%9}, {%0,%1,%2,%3};"
                 : "+f"(c[0]), "+f"(c[1]), "+f"(c[2]), "+f"(c[3])
                 : "r"(a0), "r"(a1), "r"(a2), "r"(a3), "r"(b0), "r"(b1));
}

// ---------------- CSR build --------------------------------------------------
__global__ void zero_cnt_kernel(int* deg, int* dstc) {
    int i = blockIdx.x * blockDim.x + threadIdx.x;
    if (i < NNODE) { deg[i] = 0; dstc[i] = 0; }
}
__global__ void cnt_kernel(const int* __restrict__ src, const int* __restrict__ dst,
                           int* __restrict__ deg, int* __restrict__ dstc) {
    int e = blockIdx.x * blockDim.x + threadIdx.x;
    if (e < NEDGE) {
        atomicAdd(&deg[src[e]], 1);
        atomicAdd(&dstc[dst[e]], 1);
    }
}
__global__ void dinv_kernel(const int* __restrict__ deg, float* __restrict__ dinv) {
    int i = blockIdx.x * blockDim.x + threadIdx.x;
    if (i < NNODE) {
        int d = deg[i];
        dinv[i] = (d > 0) ? rsqrtf((float)d) : 0.f;
    }
}
// single-block exclusive scan over cnt -> off, cursor (warp-shuffle version)
__global__ __launch_bounds__(1024) void scan_kernel(
    const int* __restrict__ cnt, int* __restrict__ off, int* __restrict__ cursor)
{
    __shared__ int wsum[32];
    const int tid = threadIdx.x;
    const int lane = tid & 31, wid = tid >> 5;
    const int CH = (NNODE + 1023) / 1024;   // 10
    int base = tid * CH;
    int local[CH];
    int sum = 0;
#pragma unroll
    for (int j = 0; j < CH; j++) {
        int i = base + j;
        int v = (i < NNODE) ? cnt[i] : 0;
        local[j] = sum;
        sum += v;
    }
    // warp inclusive scan of per-thread sums
    int inc = sum;
#pragma unroll
    for (int d = 1; d < 32; d <<= 1) {
        int v = __shfl_up_sync(0xffffffffu, inc, d);
        if (lane >= d) inc += v;
    }
    if (lane == 31) wsum[wid] = inc;
    __syncthreads();
    if (wid == 0) {
        int w = wsum[lane];
        int wi = w;
#pragma unroll
        for (int d = 1; d < 32; d <<= 1) {
            int v = __shfl_up_sync(0xffffffffu, wi, d);
            if (lane >= d) wi += v;
        }
        wsum[lane] = wi - w;   // exclusive
    }
    __syncthreads();
    int pre = wsum[wid] + (inc - sum);   // exclusive prefix for this thread
#pragma unroll
    for (int j = 0; j < CH; j++) {
        int i = base + j;
        if (i < NNODE) {
            int o = pre + local[j];
            off[i] = o;
            cursor[i] = o;
        }
    }
    if (tid == 1023) off[NNODE] = pre + sum;
}
__global__ void fill_kernel(const int* __restrict__ src, const int* __restrict__ dst,
                            const float* __restrict__ dinv, int* __restrict__ cursor,
                            int* __restrict__ esrc, float* __restrict__ ew) {
    int e = blockIdx.x * blockDim.x + threadIdx.x;
    if (e < NEDGE) {
        int s = src[e], d = dst[e];
        int pos = atomicAdd(&cursor[d], 1);
        esrc[pos] = s;
        ew[pos] = -dinv[s] * dinv[d];
    }
}

// ---------------- gather: S[d] = sum_e w_e * G[src_e], warp per node ---------
__global__ void gather_kernel(const int* __restrict__ off, const int* __restrict__ esrc,
                              const float* __restrict__ ew, const float* __restrict__ G,
                              float* __restrict__ S)
{
    int node = blockIdx.x * 8 + (threadIdx.x >> 5);
    int lane = threadIdx.x & 31;
    if (node >= NNODE) return;
    int beg = off[node], end = off[node + 1];
    const float4* G4 = (const float4*)G;
    float4 acc = make_float4(0.f, 0.f, 0.f, 0.f);
    for (int base = beg; base < end; base += 32) {
        int idx = base + lane;
        int   se = 0;
        float we = 0.f;
        if (idx < end) { se = __ldg(&esrc[idx]); we = __ldg(&ew[idx]); }
        int n = min(32, end - base);
        for (int j = 0; j < n; j++) {
            int   sj = __shfl_sync(0xffffffffu, se, j);
            float wj = __shfl_sync(0xffffffffu, we, j);
            float4 v = __ldg(&G4[sj * 32 + lane]);
            acc.x += wj * v.x; acc.y += wj * v.y;
            acc.z += wj * v.z; acc.w += wj * v.w;
        }
    }
    ((float4*)S)[node * 32 + lane] = acc;
}

// ---------------- Wt transpose -> fp16 K-major -------------------------------
__global__ void transpose_wt_kernel(const float* __restrict__ Wt, __half* __restrict__ WtT) {
    __shared__ float t[32][33];
    int kb = blockIdx.x * 32, nb = blockIdx.y * 32;
    int x = threadIdx.x, y = threadIdx.y;     // block (32, 8)
#pragma unroll
    for (int j = 0; j < 32; j += 8) {
        int k = kb + y + j;
        t[y + j][x] = (k < NNODE) ? Wt[(size_t)k * INC + nb + x] : 0.f;
    }
    __syncthreads();
#pragma unroll
    for (int j = 0; j < 32; j += 8) {
        int k = kb + x;
        int n = nb + y + j;
        if (k < NNODE) WtT[(size_t)n * NNODE + k] = __float2half_rn(t[x][y + j]);
    }
}

// ---------------- big GEMM: h = relu(x @ Wt + bt) via mma.sync fp16 ---------
// A [10000,10000] f32 row-major (converted to fp16 on load);
// BT [256,10000] fp16 (k contiguous per n).
// CTA: 128 threads (4 warps), tile 80(M) x 256(N); warp tile 80 x 64.
// smem rows: 32B (16 halfs) per row; 16B chunk c in {0,1} swizzled: c ^= (r>>2)&1.
extern __shared__ char g_dyn_smem[];

__global__ __launch_bounds__(128) void gemm_big_mma(
    const float* __restrict__ A, const __half* __restrict__ BT,
    const float* __restrict__ bias, float* __restrict__ C)
{
    char* smem = g_dyn_smem;
    const uint32_t sbase = smem_u32(smem);
    const int tid  = threadIdx.x;
    const int lane = tid & 31;
    const int w    = tid >> 5;
    const int row0 = blockIdx.x * BM;

    float c[5][8][4];
#pragma unroll
    for (int i = 0; i < 5; i++)
#pragma unroll
        for (int j = 0; j < 8; j++)
#pragma unroll
            for (int q = 0; q < 4; q++) c[i][j][q] = 0.f;

    // A register staging: 160 chunks (16B fp16 = 8 k-values); chunk i: r=i>>1, half c=i&1
    float4 ra0[2], ra1[2];

    auto ldgA = [&](int k0) {
        {
            int r = tid >> 1, kc = tid & 1;
            const float* p = A + (size_t)(row0 + r) * NNODE + k0 + kc * 8;
            ra0[0] = *(const float4*)p;
            ra0[1] = *(const float4*)(p + 4);
        }
        if (tid < 32) {
            int i = 128 + tid;
            int r = i >> 1, kc = i & 1;
            const float* p = A + (size_t)(row0 + r) * NNODE + k0 + kc * 8;
            ra1[0] = *(const float4*)p;
            ra1[1] = *(const float4*)(p + 4);
        }
    };
    auto cvt_store = [&](char* base, int r, int kc, float4 v0, float4 v1) {
        __half2 h0 = __floats2half2_rn(v0.x, v0.y);
        __half2 h1 = __floats2half2_rn(v0.z, v0.w);
        __half2 h2 = __floats2half2_rn(v1.x, v1.y);
        __half2 h3 = __floats2half2_rn(v1.z, v1.w);
        uint4 u;
        u.x = *(uint32_t*)&h0; u.y = *(uint32_t*)&h1;
        u.z = *(uint32_t*)&h2; u.w = *(uint32_t*)&h3;
        int s = kc ^ ((r >> 2) & 1);
        *(uint4*)(base + r * 32 + s * 16) = u;
    };
    auto stsA = [&](int stage) {
        char* base = smem + stage * STAGE_BYTES;
        cvt_store(base, tid >> 1, tid & 1, ra0[0], ra0[1]);
        if (tid < 32) {
            int i = 128 + tid;
            cvt_store(base, i >> 1, i & 1, ra1[0], ra1[1]);
        }
    };
    // B cp.async staging: 512 chunks (16B = 8 halfs); chunk i: n=i>>1, c=i&1
    auto cpB = [&](int stage, int k0) {
        uint32_t base = sbase + stage * STAGE_BYTES + A_BYTES;
#pragma unroll
        for (int it = 0; it < 4; it++) {
            int i  = tid + it * 128;
            int n  = i >> 1;
            int kc = i & 1;
            int s  = kc ^ ((n >> 2) & 1);
            cp_async16(base + (uint32_t)(n * 32 + s * 16),
                       BT + (size_t)n * NNODE + k0 + kc * 8);
        }
    };

    // ldmatrix lane->address components
    // A (x4: m0 rows0-7 k0-7, m1 rows8-15 k0-7, m2 rows0-7 k8-15, m3 rows8-15 k8-15)
    const int a_row  = (lane & 7) + ((lane >> 3) & 1) * 8;
    const int a_c    = (lane >> 4) & 1;
    // B (x4: m0 n0-7 k0-7 (b0), m1 n0-7 k8-15 (b1), m2 n8-15 k0-7, m3 n8-15 k8-15)
    const int b_nl   = (lane & 7) + ((lane >> 4) & 1) * 8;
    const int b_c    = (lane >> 3) & 1;

    cpB(0, 0);  CP_COMMIT();
    cpB(1, 16); CP_COMMIT();
    cpB(2, 32); CP_COMMIT();
    ldgA(0);        stsA(0);
    ldgA(1 * BK);   stsA(1);
    ldgA(2 * BK);   stsA(2);
    ldgA(3 * BK);

    for (int kt = 0; kt < NKT; kt++) {
        CP_WAIT2();
        __syncthreads();

        const int kn = kt + 3;
        if (kn < NKT) {
            cpB(kn & 3, kn * BK);
            stsA(kn & 3);
        }
        CP_COMMIT();
        if (kt + 4 < NKT) ldgA((kt + 4) * BK);

        const uint32_t abase = sbase + (uint32_t)(kt & 3) * STAGE_BYTES;
        const uint32_t bbase = abase + A_BYTES;

        uint32_t bb[4][4];
#pragma unroll
        for (int np = 0; np < 4; np++) {
            int n = w * 64 + np * 16 + b_nl;
            int s = b_c ^ ((n >> 2) & 1);
            ldsm4(bb[np][0], bb[np][1], bb[np][2], bb[np][3],
                  bbase + (uint32_t)(n * 32 + s * 16));
        }
#pragma unroll
        for (int mf = 0; mf < 5; mf++) {
            int r = mf * 16 + a_row;
            int s = a_c ^ ((r >> 2) & 1);
            uint32_t a0, a1, a2, a3;
            ldsm4(a0, a1, a2, a3, abase + (uint32_t)(r * 32 + s * 16));
#pragma unroll
            for (int np = 0; np < 4; np++) {
                mma_f16(c[mf][np * 2],     a0, a1, a2, a3, bb[np][0], bb[np][1]);
                mma_f16(c[mf][np * 2 + 1], a0, a1, a2, a3, bb[np][2], bb[np][3]);
            }
        }
    }

    // epilogue: bias + relu
    const int g = lane >> 2;
    const int t2 = (lane & 3) * 2;
#pragma unroll
    for (int mf = 0; mf < 5; mf++) {
        int r = row0 + mf * 16 + g;
#pragma unroll
        for (int nf = 0; nf < 8; nf++) {
            int col = w * 64 + nf * 8 + t2;
            float2 bb = *(const float2*)(bias + col);
            float2 o0, o1;
            o0.x = fmaxf(c[mf][nf][0] + bb.x, 0.f);
            o0.y = fmaxf(c[mf][nf][1] + bb.y, 0.f);
            o1.x = fmaxf(c[mf][nf][2] + bb.x, 0.f);
            o1.y = fmaxf(c[mf][nf][3] + bb.y, 0.f);
            *(float2*)(C + (size_t)r * INC + col)       = o0;
            *(float2*)(C + (size_t)(r + 8) * INC + col) = o1;
        }
    }
}

// ---------------- merged small GEMM 1: [G|H] = h @ [W1_1 | W0_1] -------------
// block (64, 8) = 512 threads; thread = (row ty, 4 cols tx). K=INC=256.
__global__ __launch_bounds__(512) void gemm_s1_kernel(
    const float* __restrict__ A, const float* __restrict__ B1,
    const float* __restrict__ B0, float* __restrict__ G, float* __restrict__ H)
{
    __shared__ float sA[8][INC];
    const int tx = threadIdx.x;       // 0..63
    const int ty = threadIdx.y;       // 0..7
    const int tid = ty * 64 + tx;
    const int row0 = blockIdx.x * 8;

    const float4* A4 = (const float4*)A;
    {   // 512 float4 loads, one per thread
        int r = tid >> 6;             // /64
        int col = tid & 63;
        ((float4*)&sA[r][0])[col] = A4[(size_t)(row0 + r) * 64 + col];
    }
    __syncthreads();

    const float4* Bp = (tx < 32) ? (const float4*)B1 : (const float4*)B0;
    const int bx = tx & 31;
    float4 acc = make_float4(0.f, 0.f, 0.f, 0.f);
#pragma unroll 8
    for (int k = 0; k < INC; k++) {
        float a = sA[ty][k];
        float4 b = __ldg(&Bp[k * 32 + bx]);
        acc.x += a * b.x; acc.y += a * b.y; acc.z += a * b.z; acc.w += a * b.w;
    }
    int r = row0 + ty;
    float4* O = (tx < 32) ? (float4*)G : (float4*)H;
    O[(size_t)r * 32 + bx] = acc;
}

// ---------------- merged small GEMM 2: [G2|H2] = h2 @ [W1mu|W1ls|W0mu|W0ls] --
// block (64, 8) = 512 threads. K=HID=128. tx quadrant selects matrix.
__global__ __launch_bounds__(512) void gemm_s2_kernel(
    const float* __restrict__ A,
    const float* __restrict__ W1mu, const float* __restrict__ W1ls,
    const float* __restrict__ W0mu, const float* __restrict__ W0ls,
    float* __restrict__ G2, float* __restrict__ H2)
{
    __shared__ float sA[8][HID];
    const int tx = threadIdx.x;
    const int ty = threadIdx.y;
    const int tid = ty * 64 + tx;
    const int row0 = blockIdx.x * 8;

    const float4* A4 = (const float4*)A;
    if (tid < 256) {   // 8 rows x 32 float4
        int r = tid >> 5;
        int col = tid & 31;
        ((float4*)&sA[r][0])[col] = A4[(size_t)(row0 + r) * 32 + col];
    }
    __syncthreads();

    const int q = tx >> 4;            // 0..3
    const int t16 = tx & 15;
    const float4* Bq = (q == 0) ? (const float4*)W1mu :
                       (q == 1) ? (const float4*)W1ls :
                       (q == 2) ? (const float4*)W0mu : (const float4*)W0ls;
    float4 acc = make_float4(0.f, 0.f, 0.f, 0.f);
#pragma unroll 8
    for (int k = 0; k < HID; k++) {
        float a = sA[ty][k];
        float4 b = __ldg(&Bq[k * 16 + t16]);
        acc.x += a * b.x; acc.y += a * b.y; acc.z += a * b.z; acc.w += a * b.w;
    }
    int r = row0 + ty;
    if (q < 2) ((float4*)G2)[(size_t)r * 32 + q * 16 + t16] = acc;
    else       ((float4*)H2)[(size_t)r * 32 + (q - 2) * 16 + t16] = acc;
}

// ---------------- elementwise epilogues -------------------------------------
__global__ void h2_ep_kernel(const float* __restrict__ HW, const float* __restrict__ S1,
                             const float* __restrict__ b1, float* __restrict__ H2)
{
    int i = blockIdx.x * blockDim.x + threadIdx.x;   // float4 index
    if (i >= NNODE * 32) return;
    int c4 = i & 31;
    float4 h = ((const float4*)HW)[i];
    float4 s = ((const float4*)S1)[i];
    float4 b = ((const float4*)b1)[c4];
    float4 o;
    o.x = fmaxf(h.x + s.x + b.x, 0.f);
    o.y = fmaxf(h.y + s.y + b.y, 0.f);
    o.z = fmaxf(h.z + s.z + b.z, 0.f);
    o.w = fmaxf(h.w + s.w + b.w, 0.f);
    ((float4*)H2)[i] = o;
}

__global__ void out_ep_kernel(const float* __restrict__ HW2, const float* __restrict__ S2,
                              const float* __restrict__ bmu, const float* __restrict__ bls,
                              float* __restrict__ out)
{
    int i = blockIdx.x * blockDim.x + threadIdx.x;   // node*16 + c4
    if (i >= NNODE * 16) return;
    int n = i >> 4;
    int c4 = i & 15;
    float4 hm = ((const float4*)HW2)[n * 32 + c4];
    float4 sm = ((const float4*)S2)[n * 32 + c4];
    float4 bm = ((const float4*)bmu)[c4];
    float4 hl = ((const float4*)HW2)[n * 32 + 16 + c4];
    float4 sl = ((const float4*)S2)[n * 32 + 16 + c4];
    float4 bl = ((const float4*)bls)[c4];
    float4 om, ol;
    om.x = hm.x + sm.x + bm.x; om.y = hm.y + sm.y + bm.y;
    om.z = hm.z + sm.z + bm.z; om.w = hm.w + sm.w + bm.w;
    ol.x = hl.x + sl.x + bl.x; ol.y = hl.y + sl.y + bl.y;
    ol.z = hl.z + sl.z + bl.z; ol.w = hl.w + sl.w + bl.w;
    ((float4*)out)[n * 16 + c4] = om;
    ((float4*)out)[NNODE * 16 + n * 16 + c4] = ol;
}

// ---------------- launch -----------------------------------------------------
extern "C" void kernel_launch(void* const* d_in, const int* in_sizes, int n_in,
                              void* d_out, int out_size)
{
    const float* x     = (const float*)d_in[0];
    const int*   ei    = (const int*)  d_in[1];
    const float* Wt    = (const float*)d_in[2];
    const float* bt    = (const float*)d_in[3];
    const float* W0_1  = (const float*)d_in[4];
    const float* W1_1  = (const float*)d_in[5];
    const float* b1    = (const float*)d_in[6];
    const float* W0_mu = (const float*)d_in[7];
    const float* W1_mu = (const float*)d_in[8];
    const float* b_mu  = (const float*)d_in[9];
    const float* W0_ls = (const float*)d_in[10];
    const float* W1_ls = (const float*)d_in[11];
    const float* b_ls  = (const float*)d_in[12];
    float* out = (float*)d_out;

    const int* src = ei;
    const int* dst = ei + NEDGE;

    float *hP, *g1P, *hwP, *s1P, *h2P, *g2P, *hw2P, *s2P, *dinvP, *ewP;
    __half* wttP;
    int *degP, *dstcP, *offP, *curP, *esrcP;
    cudaGetSymbolAddress((void**)&hP,    g_h);
    cudaGetSymbolAddress((void**)&wttP,  g_WtT);
    cudaGetSymbolAddress((void**)&g1P,   g_g1);
    cudaGetSymbolAddress((void**)&hwP,   g_hw);
    cudaGetSymbolAddress((void**)&s1P,   g_s1);
    cudaGetSymbolAddress((void**)&h2P,   g_h2);
    cudaGetSymbolAddress((void**)&g2P,   g_g2);
    cudaGetSymbolAddress((void**)&hw2P,  g_hw2);
    cudaGetSymbolAddress((void**)&s2P,   g_s2);
    cudaGetSymbolAddress((void**)&dinvP, g_dinv);
    cudaGetSymbolAddress((void**)&degP,  g_deg);
    cudaGetSymbolAddress((void**)&dstcP, g_dstc);
    cudaGetSymbolAddress((void**)&offP,  g_off);
    cudaGetSymbolAddress((void**)&curP,  g_cur);
    cudaGetSymbolAddress((void**)&esrcP, g_esrc);
    cudaGetSymbolAddress((void**)&ewP,   g_ew);

    // --- CSR build (by dst) + dinv ---
    zero_cnt_kernel<<<(NNODE + 255) / 256, 256>>>(degP, dstcP);
    cnt_kernel<<<(NEDGE + 255) / 256, 256>>>(src, dst, degP, dstcP);
    dinv_kernel<<<(NNODE + 255) / 256, 256>>>(degP, dinvP);
    scan_kernel<<<1, 1024>>>(dstcP, offP, curP);
    fill_kernel<<<(NEDGE + 255) / 256, 256>>>(src, dst, dinvP, curP, esrcP, ewP);

    // --- transpose Wt -> fp16 K-major ---
    {
        dim3 grid((NNODE + 31) / 32, INC / 32);
        transpose_wt_kernel<<<grid, dim3(32, 8)>>>(Wt, wttP);
    }
    // --- h = relu(x @ Wt + bt) via mma.sync fp16 ---
    {
        cudaFuncSetAttribute(gemm_big_mma,
                             cudaFuncAttributeMaxDynamicSharedMemorySize, GSMEM_TOTAL);
        gemm_big_mma<<<NNODE / BM, 128, GSMEM_TOTAL>>>(x, wttP, bt, hP);
    }
    // --- [g1 | hw] = h @ [W1_1 | W0_1] ---
    gemm_s1_kernel<<<NNODE / 8, dim3(64, 8)>>>(hP, W1_1, W0_1, g1P, hwP);
    // --- s1 = gather(w * g1[src]) ---
    gather_kernel<<<(NNODE + 7) / 8, 256>>>(offP, esrcP, ewP, g1P, s1P);
    // --- h2 = relu(hw + s1 + b1) ---
    h2_ep_kernel<<<(NNODE * 32 + 255) / 256, 256>>>(hwP, s1P, b1, h2P);
    // --- [g2 | hw2] = h2 @ [W1_mu|W1_ls|W0_mu|W0_ls] ---
    gemm_s2_kernel<<<NNODE / 8, dim3(64, 8)>>>(h2P, W1_mu, W1_ls, W0_mu, W0_ls, g2P, hw2P);
    // --- s2 = gather(w * g2[src]) ---
    gather_kernel<<<(NNODE + 7) / 8, 256>>>(offP, esrcP, ewP, g2P, s2P);
    // --- out = [hw2_mu + s2_mu + b_mu | hw2_ls + s2_ls + b_ls] ---
    out_ep_kernel<<<(NNODE * 16 + 255) / 256, 256>>>(hw2P, s2P, b_mu, b_ls, out);
}

// round 11
// speedup vs baseline: 3.3779x; 1.2534x over previous
#include <cuda_runtime.h>
#include <cuda_fp16.h>
#include <cstdint>

#define NNODE 10000
#define INC   256
#define HID   128      // 2*OUT_C
#define OUTC  64
#define NEDGE 640000

// ---- big GEMM tiling (mma.sync fp16, m16n8k16) ----
#define BM 80
#define BK 16
#define NKT (NNODE / BK)          // 625
#define A_BYTES (BM * BK * 2)     // 2560 (fp16)
#define B_BYTES (INC * BK * 2)    // 8192 (fp16)
#define STAGE_BYTES (A_BYTES + B_BYTES)     // 10752
#define NSTAGE 4
#define GSMEM_TOTAL (NSTAGE * STAGE_BYTES)  // 43008

// ---- small GEMM tiling ----
#define SBM 80
#define SBN 128
#define SA_BYTES (SBM * 16 * 2)            // 2560
#define SB_BYTES (SBN * 16 * 2)            // 4096
#define SSTAGE (SA_BYTES + SB_BYTES)       // 6656

// ---------------- scratch (device globals; no allocations allowed) ----------
__device__ __half g_h16 [NNODE * INC];  // relu(x@Wt+bt) fp16
__device__ __half g_WtT [INC * NNODE];  // Wt transposed (K-major), fp16
__device__ __half g_BT1 [HID * INC];    // W1_1^T fp16  [n][k]
__device__ __half g_BT0 [HID * INC];    // W0_1^T fp16
__device__ __half g_BT2g[HID * HID];    // [W1_mu|W1_ls]^T fp16
__device__ __half g_BT2h[HID * HID];    // [W0_mu|W0_ls]^T fp16
__device__ float  g_g1 [NNODE * HID];   // h @ W1_1
__device__ float  g_hw [NNODE * HID];   // h @ W0_1
__device__ float  g_s1 [NNODE * HID];   // gather of w*g1[src]
__device__ __half g_h216[NNODE * HID];  // relu(hw + s1 + b1) fp16
__device__ float  g_g2 [NNODE * HID];   // [h2@W1_mu | h2@W1_ls]
__device__ float  g_hw2[NNODE * HID];   // [h2@W0_mu | h2@W0_ls]
__device__ float  g_s2 [NNODE * HID];   // gather of w*g2[src]
__device__ float  g_dinv[NNODE];
__device__ int    g_deg [NNODE];
__device__ int    g_dstc[NNODE];
__device__ int    g_off [NNODE + 1];
__device__ int    g_cur [NNODE];
__device__ int    g_esrc[NEDGE];
__device__ float  g_ew  [NEDGE];

// ======================= helpers ============================================
__device__ __forceinline__ uint32_t smem_u32(const void* p) {
    uint32_t a;
    asm("{ .reg .u64 t; cvta.to.shared.u64 t, %1; cvt.u32.u64 %0, t; }" : "=r"(a) : "l"(p));
    return a;
}
__device__ __forceinline__ void cp_async16(uint32_t dst, const void* src) {
    asm volatile("cp.async.cg.shared.global [%0], [%1], 16;" :: "r"(dst), "l"(src));
}
#define CP_COMMIT() asm volatile("cp.async.commit_group;" ::: "memory")
#define CP_WAIT2()  asm volatile("cp.async.wait_group 2;" ::: "memory")
#define CP_WAIT1()  asm volatile("cp.async.wait_group 1;" ::: "memory")

__device__ __forceinline__ void ldsm4(uint32_t& r0, uint32_t& r1, uint32_t& r2, uint32_t& r3,
                                      uint32_t addr) {
    asm volatile("ldmatrix.sync.aligned.m8n8.x4.shared.b16 {%0,%1,%2,%3}, [%4];"
                 : "=r"(r0), "=r"(r1), "=r"(r2), "=r"(r3) : "r"(addr));
}
__device__ __forceinline__ void mma_f16(float* c, uint32_t a0, uint32_t a1, uint32_t a2,
                                        uint32_t a3, uint32_t b0, uint32_t b1) {
    asm volatile("mma.sync.aligned.m16n8k16.row.col.f32.f16.f16.f32 "
                 "{%0,%1,%2,%3}, {%4,%5,%6,%7}, {%8,%9}, {%0,%1,%2,%3};"
                 : "+f"(c[0]), "+f"(c[1]), "+f"(c[2]), "+f"(c[3])
                 : "r"(a0), "r"(a1), "r"(a2), "r"(a3), "r"(b0), "r"(b1));
}

// ---------------- CSR build --------------------------------------------------
__global__ void zero_cnt_kernel(int* deg, int* dstc) {
    int i = blockIdx.x * blockDim.x + threadIdx.x;
    if (i < NNODE) { deg[i] = 0; dstc[i] = 0; }
}
__global__ void cnt_kernel(const int* __restrict__ src, const int* __restrict__ dst,
                           int* __restrict__ deg, int* __restrict__ dstc) {
    int e = blockIdx.x * blockDim.x + threadIdx.x;
    if (e < NEDGE) {
        atomicAdd(&deg[src[e]], 1);
        atomicAdd(&dstc[dst[e]], 1);
    }
}
__global__ void dinv_kernel(const int* __restrict__ deg, float* __restrict__ dinv) {
    int i = blockIdx.x * blockDim.x + threadIdx.x;
    if (i < NNODE) {
        int d = deg[i];
        dinv[i] = (d > 0) ? rsqrtf((float)d) : 0.f;
    }
}
// single-block exclusive scan (coalesced via smem staging)
__global__ __launch_bounds__(1024) void scan_kernel(
    const int* __restrict__ cnt, int* __restrict__ off, int* __restrict__ cursor)
{
    __shared__ int sbuf[NNODE];
    __shared__ int wsum[32];
    const int tid = threadIdx.x;
    const int lane = tid & 31, wid = tid >> 5;
    for (int i = tid; i < NNODE; i += 1024) sbuf[i] = cnt[i];
    __syncthreads();

    const int CH = (NNODE + 1023) / 1024;   // 10
    int base = tid * CH;
    int local[CH];
    int sum = 0;
#pragma unroll
    for (int j = 0; j < CH; j++) {
        int i = base + j;
        int v = (i < NNODE) ? sbuf[i] : 0;
        local[j] = sum;
        sum += v;
    }
    int inc = sum;
#pragma unroll
    for (int d = 1; d < 32; d <<= 1) {
        int v = __shfl_up_sync(0xffffffffu, inc, d);
        if (lane >= d) inc += v;
    }
    if (lane == 31) wsum[wid] = inc;
    __syncthreads();
    if (wid == 0) {
        int w = wsum[lane];
        int wi = w;
#pragma unroll
        for (int d = 1; d < 32; d <<= 1) {
            int v = __shfl_up_sync(0xffffffffu, wi, d);
            if (lane >= d) wi += v;
        }
        wsum[lane] = wi - w;
    }
    __syncthreads();
    int pre = wsum[wid] + (inc - sum);
#pragma unroll
    for (int j = 0; j < CH; j++) {
        int i = base + j;
        if (i < NNODE) sbuf[i] = pre + local[j];
    }
    __syncthreads();
    for (int i = tid; i < NNODE; i += 1024) {
        int o = sbuf[i];
        off[i] = o;
        cursor[i] = o;
    }
    if (tid == 1023) off[NNODE] = pre + sum;
}
__global__ void fill_kernel(const int* __restrict__ src, const int* __restrict__ dst,
                            const float* __restrict__ dinv, int* __restrict__ cursor,
                            int* __restrict__ esrc, float* __restrict__ ew) {
    int e = blockIdx.x * blockDim.x + threadIdx.x;
    if (e < NEDGE) {
        int s = src[e], d = dst[e];
        int pos = atomicAdd(&cursor[d], 1);
        esrc[pos] = s;
        ew[pos] = -dinv[s] * dinv[d];
    }
}

// ---------------- gather: S[d] = sum_e w_e * G[src_e], warp per node ---------
__global__ void gather_kernel(const int* __restrict__ off, const int* __restrict__ esrc,
                              const float* __restrict__ ew, const float* __restrict__ G,
                              float* __restrict__ S)
{
    int node = blockIdx.x * 8 + (threadIdx.x >> 5);
    int lane = threadIdx.x & 31;
    if (node >= NNODE) return;
    int beg = off[node], end = off[node + 1];
    const float4* G4 = (const float4*)G;
    float4 acc = make_float4(0.f, 0.f, 0.f, 0.f);
    for (int base = beg; base < end; base += 32) {
        int idx = base + lane;
        int   se = 0;
        float we = 0.f;
        if (idx < end) { se = __ldg(&esrc[idx]); we = __ldg(&ew[idx]); }
        int n = min(32, end - base);
        for (int j = 0; j < n; j++) {
            int   sj = __shfl_sync(0xffffffffu, se, j);
            float wj = __shfl_sync(0xffffffffu, we, j);
            float4 v = __ldg(&G4[sj * 32 + lane]);
            acc.x += wj * v.x; acc.y += wj * v.y;
            acc.z += wj * v.z; acc.w += wj * v.w;
        }
    }
    ((float4*)S)[node * 32 + lane] = acc;
}

// ---------------- Wt transpose -> fp16 K-major -------------------------------
__global__ void transpose_wt_kernel(const float* __restrict__ Wt, __half* __restrict__ WtT) {
    __shared__ float t[32][33];
    int kb = blockIdx.x * 32, nb = blockIdx.y * 32;
    int x = threadIdx.x, y = threadIdx.y;     // block (32, 8)
#pragma unroll
    for (int j = 0; j < 32; j += 8) {
        int k = kb + y + j;
        t[y + j][x] = (k < NNODE) ? Wt[(size_t)k * INC + nb + x] : 0.f;
    }
    __syncthreads();
#pragma unroll
    for (int j = 0; j < 32; j += 8) {
        int k = kb + x;
        int n = nb + y + j;
        if (k < NNODE) WtT[(size_t)n * NNODE + k] = __float2half_rn(t[x][y + j]);
    }
}

// ---------------- small weight transpose: BT[(n0+n)*K + k] = W[k*N + n] ------
__global__ void wconv_kernel(const float* __restrict__ W, __half* __restrict__ BT,
                             int K, int N, int n0) {
    int i = blockIdx.x * blockDim.x + threadIdx.x;
    if (i < K * N) {
        int k = i / N, n = i - k * N;
        BT[(size_t)(n0 + n) * K + k] = __float2half_rn(W[i]);
    }
}

// ---------------- big GEMM: h16 = relu(x @ Wt + bt) via mma.sync fp16 -------
extern __shared__ char g_dyn_smem[];

__global__ __launch_bounds__(128) void gemm_big_mma(
    const float* __restrict__ A, const __half* __restrict__ BT,
    const float* __restrict__ bias, __half* __restrict__ C)
{
    char* smem = g_dyn_smem;
    const uint32_t sbase = smem_u32(smem);
    const int tid  = threadIdx.x;
    const int lane = tid & 31;
    const int w    = tid >> 5;
    const int row0 = blockIdx.x * BM;

    float c[5][8][4];
#pragma unroll
    for (int i = 0; i < 5; i++)
#pragma unroll
        for (int j = 0; j < 8; j++)
#pragma unroll
            for (int q = 0; q < 4; q++) c[i][j][q] = 0.f;

    float4 ra0[2], ra1[2];

    auto ldgA = [&](int k0) {
        {
            int r = tid >> 1, kc = tid & 1;
            const float* p = A + (size_t)(row0 + r) * NNODE + k0 + kc * 8;
            ra0[0] = *(const float4*)p;
            ra0[1] = *(const float4*)(p + 4);
        }
        if (tid < 32) {
            int i = 128 + tid;
            int r = i >> 1, kc = i & 1;
            const float* p = A + (size_t)(row0 + r) * NNODE + k0 + kc * 8;
            ra1[0] = *(const float4*)p;
            ra1[1] = *(const float4*)(p + 4);
        }
    };
    auto cvt_store = [&](char* base, int r, int kc, float4 v0, float4 v1) {
        __half2 h0 = __floats2half2_rn(v0.x, v0.y);
        __half2 h1 = __floats2half2_rn(v0.z, v0.w);
        __half2 h2 = __floats2half2_rn(v1.x, v1.y);
        __half2 h3 = __floats2half2_rn(v1.z, v1.w);
        uint4 u;
        u.x = *(uint32_t*)&h0; u.y = *(uint32_t*)&h1;
        u.z = *(uint32_t*)&h2; u.w = *(uint32_t*)&h3;
        int s = kc ^ ((r >> 2) & 1);
        *(uint4*)(base + r * 32 + s * 16) = u;
    };
    auto stsA = [&](int stage) {
        char* base = smem + stage * STAGE_BYTES;
        cvt_store(base, tid >> 1, tid & 1, ra0[0], ra0[1]);
        if (tid < 32) {
            int i = 128 + tid;
            cvt_store(base, i >> 1, i & 1, ra1[0], ra1[1]);
        }
    };
    auto cpB = [&](int stage, int k0) {
        uint32_t base = sbase + stage * STAGE_BYTES + A_BYTES;
#pragma unroll
        for (int it = 0; it < 4; it++) {
            int i  = tid + it * 128;
            int n  = i >> 1;
            int kc = i & 1;
            int s  = kc ^ ((n >> 2) & 1);
            cp_async16(base + (uint32_t)(n * 32 + s * 16),
                       BT + (size_t)n * NNODE + k0 + kc * 8);
        }
    };

    const int a_row  = (lane & 7) + ((lane >> 3) & 1) * 8;
    const int a_c    = (lane >> 4) & 1;
    const int b_nl   = (lane & 7) + ((lane >> 4) & 1) * 8;
    const int b_c    = (lane >> 3) & 1;

    cpB(0, 0);  CP_COMMIT();
    cpB(1, 16); CP_COMMIT();
    cpB(2, 32); CP_COMMIT();
    ldgA(0);        stsA(0);
    ldgA(1 * BK);   stsA(1);
    ldgA(2 * BK);   stsA(2);
    ldgA(3 * BK);

    for (int kt = 0; kt < NKT; kt++) {
        CP_WAIT2();
        __syncthreads();

        const int kn = kt + 3;
        if (kn < NKT) {
            cpB(kn & 3, kn * BK);
            stsA(kn & 3);
        }
        CP_COMMIT();
        if (kt + 4 < NKT) ldgA((kt + 4) * BK);

        const uint32_t abase = sbase + (uint32_t)(kt & 3) * STAGE_BYTES;
        const uint32_t bbase = abase + A_BYTES;

        uint32_t bb[4][4];
#pragma unroll
        for (int np = 0; np < 4; np++) {
            int n = w * 64 + np * 16 + b_nl;
            int s = b_c ^ ((n >> 2) & 1);
            ldsm4(bb[np][0], bb[np][1], bb[np][2], bb[np][3],
                  bbase + (uint32_t)(n * 32 + s * 16));
        }
#pragma unroll
        for (int mf = 0; mf < 5; mf++) {
            int r = mf * 16 + a_row;
            int s = a_c ^ ((r >> 2) & 1);
            uint32_t a0, a1, a2, a3;
            ldsm4(a0, a1, a2, a3, abase + (uint32_t)(r * 32 + s * 16));
#pragma unroll
            for (int np = 0; np < 4; np++) {
                mma_f16(c[mf][np * 2],     a0, a1, a2, a3, bb[np][0], bb[np][1]);
                mma_f16(c[mf][np * 2 + 1], a0, a1, a2, a3, bb[np][2], bb[np][3]);
            }
        }
    }

    // epilogue: bias + relu -> fp16
    const int g = lane >> 2;
    const int t2 = (lane & 3) * 2;
#pragma unroll
    for (int mf = 0; mf < 5; mf++) {
        int r = row0 + mf * 16 + g;
#pragma unroll
        for (int nf = 0; nf < 8; nf++) {
            int col = w * 64 + nf * 8 + t2;
            float2 bb = *(const float2*)(bias + col);
            __half2 p0 = __floats2half2_rn(fmaxf(c[mf][nf][0] + bb.x, 0.f),
                                           fmaxf(c[mf][nf][1] + bb.y, 0.f));
            __half2 p1 = __floats2half2_rn(fmaxf(c[mf][nf][2] + bb.x, 0.f),
                                           fmaxf(c[mf][nf][3] + bb.y, 0.f));
            *(__half2*)(C + (size_t)r * INC + col)       = p0;
            *(__half2*)(C + (size_t)(r + 8) * INC + col) = p1;
        }
    }
}

// ---------------- small GEMM via mma.sync fp16 -------------------------------
// C[by][10000 x 128] = A[10000 x KK] @ BT[by][128 x KK]^T ; all fp16 in, f32 out.
// CTA: 128 threads (4 warps), tile 80(M) x 128(N); warp tile 80 x 32.
template<int KK>
__global__ __launch_bounds__(128) void sgemm_mma(
    const __half* __restrict__ A,
    const __half* __restrict__ BTa, const __half* __restrict__ BTb,
    float* __restrict__ Ca, float* __restrict__ Cb)
{
    __shared__ char smem[3 * SSTAGE];
    const uint32_t sbase = smem_u32(smem);
    const int tid  = threadIdx.x;
    const int lane = tid & 31;
    const int w    = tid >> 5;
    const int row0 = blockIdx.x * SBM;
    const __half* BT = blockIdx.y ? BTb : BTa;
    float* C = blockIdx.y ? Cb : Ca;
    const int SNKT = KK / 16;

    float c[5][4][4];
#pragma unroll
    for (int i = 0; i < 5; i++)
#pragma unroll
        for (int j = 0; j < 4; j++)
#pragma unroll
            for (int q = 0; q < 4; q++) c[i][j][q] = 0.f;

    // stage load: A 160 chunks (r=i>>1, kc=i&1), B 256 chunks
    auto ld_stage = [&](int stage, int kt) {
        uint32_t abase = sbase + (uint32_t)stage * SSTAGE;
        uint32_t bbase = abase + SA_BYTES;
        int k0 = kt * 16;
#pragma unroll
        for (int it = 0; it < 4; it++) {
            int i = tid + it * 128;
            if (i < 160) {
                int r = i >> 1, kc = i & 1;
                int s = kc ^ ((r >> 2) & 1);
                cp_async16(abase + (uint32_t)(r * 32 + s * 16),
                           A + (size_t)(row0 + r) * KK + k0 + kc * 8);
            } else if (i < 416) {
                int j = i - 160;
                int n = j >> 1, kc = j & 1;
                int s = kc ^ ((n >> 2) & 1);
                cp_async16(bbase + (uint32_t)(n * 32 + s * 16),
                           BT + (size_t)n * KK + k0 + kc * 8);
            }
        }
    };

    const int a_row  = (lane & 7) + ((lane >> 3) & 1) * 8;
    const int a_c    = (lane >> 4) & 1;
    const int b_nl   = (lane & 7) + ((lane >> 4) & 1) * 8;
    const int b_c    = (lane >> 3) & 1;

    ld_stage(0, 0); CP_COMMIT();
    ld_stage(1, 1); CP_COMMIT();

    for (int kt = 0; kt < SNKT; kt++) {
        CP_WAIT1();
        __syncthreads();
        if (kt + 2 < SNKT) ld_stage((kt + 2) % 3, kt + 2);
        CP_COMMIT();

        const uint32_t abase = sbase + (uint32_t)(kt % 3) * SSTAGE;
        const uint32_t bbase = abase + SA_BYTES;

        uint32_t bb[2][4];
#pragma unroll
        for (int np = 0; np < 2; np++) {
            int n = w * 32 + np * 16 + b_nl;
            int s = b_c ^ ((n >> 2) & 1);
            ldsm4(bb[np][0], bb[np][1], bb[np][2], bb[np][3],
                  bbase + (uint32_t)(n * 32 + s * 16));
        }
#pragma unroll
        for (int mf = 0; mf < 5; mf++) {
            int r = mf * 16 + a_row;
            int s = a_c ^ ((r >> 2) & 1);
            uint32_t a0, a1, a2, a3;
            ldsm4(a0, a1, a2, a3, abase + (uint32_t)(r * 32 + s * 16));
#pragma unroll
            for (int np = 0; np < 2; np++) {
                mma_f16(c[mf][np * 2],     a0, a1, a2, a3, bb[np][0], bb[np][1]);
                mma_f16(c[mf][np * 2 + 1], a0, a1, a2, a3, bb[np][2], bb[np][3]);
            }
        }
    }

    const int g = lane >> 2;
    const int t2 = (lane & 3) * 2;
#pragma unroll
    for (int mf = 0; mf < 5; mf++) {
        int r = row0 + mf * 16 + g;
#pragma unroll
        for (int nf = 0; nf < 4; nf++) {
            int col = w * 32 + nf * 8 + t2;
            float2 o0 = make_float2(c[mf][nf][0], c[mf][nf][1]);
            float2 o1 = make_float2(c[mf][nf][2], c[mf][nf][3]);
            *(float2*)(C + (size_t)r * HID + col)       = o0;
            *(float2*)(C + (size_t)(r + 8) * HID + col) = o1;
        }
    }
}

// ---------------- elementwise epilogues -------------------------------------
__global__ void h2_ep_kernel(const float* __restrict__ HW, const float* __restrict__ S1,
                             const float* __restrict__ b1, __half* __restrict__ H2)
{
    int i = blockIdx.x * blockDim.x + threadIdx.x;   // float4 index
    if (i >= NNODE * 32) return;
    int c4 = i & 31;
    float4 h = ((const float4*)HW)[i];
    float4 s = ((const float4*)S1)[i];
    float4 b = ((const float4*)b1)[c4];
    __half2 p0 = __floats2half2_rn(fmaxf(h.x + s.x + b.x, 0.f),
                                   fmaxf(h.y + s.y + b.y, 0.f));
    __half2 p1 = __floats2half2_rn(fmaxf(h.z + s.z + b.z, 0.f),
                                   fmaxf(h.w + s.w + b.w, 0.f));
    ((__half2*)H2)[i * 2]     = p0;
    ((__half2*)H2)[i * 2 + 1] = p1;
}

__global__ void out_ep_kernel(const float* __restrict__ HW2, const float* __restrict__ S2,
                              const float* __restrict__ bmu, const float* __restrict__ bls,
                              float* __restrict__ out)
{
    int i = blockIdx.x * blockDim.x + threadIdx.x;   // node*16 + c4
    if (i >= NNODE * 16) return;
    int n = i >> 4;
    int c4 = i & 15;
    float4 hm = ((const float4*)HW2)[n * 32 + c4];
    float4 sm = ((const float4*)S2)[n * 32 + c4];
    float4 bm = ((const float4*)bmu)[c4];
    float4 hl = ((const float4*)HW2)[n * 32 + 16 + c4];
    float4 sl = ((const float4*)S2)[n * 32 + 16 + c4];
    float4 bl = ((const float4*)bls)[c4];
    float4 om, ol;
    om.x = hm.x + sm.x + bm.x; om.y = hm.y + sm.y + bm.y;
    om.z = hm.z + sm.z + bm.z; om.w = hm.w + sm.w + bm.w;
    ol.x = hl.x + sl.x + bl.x; ol.y = hl.y + sl.y + bl.y;
    ol.z = hl.z + sl.z + bl.z; ol.w = hl.w + sl.w + bl.w;
    ((float4*)out)[n * 16 + c4] = om;
    ((float4*)out)[NNODE * 16 + n * 16 + c4] = ol;
}

// ---------------- launch -----------------------------------------------------
extern "C" void kernel_launch(void* const* d_in, const int* in_sizes, int n_in,
                              void* d_out, int out_size)
{
    const float* x     = (const float*)d_in[0];
    const int*   ei    = (const int*)  d_in[1];
    const float* Wt    = (const float*)d_in[2];
    const float* bt    = (const float*)d_in[3];
    const float* W0_1  = (const float*)d_in[4];
    const float* W1_1  = (const float*)d_in[5];
    const float* b1    = (const float*)d_in[6];
    const float* W0_mu = (const float*)d_in[7];
    const float* W1_mu = (const float*)d_in[8];
    const float* b_mu  = (const float*)d_in[9];
    const float* W0_ls = (const float*)d_in[10];
    const float* W1_ls = (const float*)d_in[11];
    const float* b_ls  = (const float*)d_in[12];
    float* out = (float*)d_out;

    const int* src = ei;
    const int* dst = ei + NEDGE;

    float *g1P, *hwP, *s1P, *g2P, *hw2P, *s2P, *dinvP, *ewP;
    __half *h16P, *wttP, *bt1P, *bt0P, *bt2gP, *bt2hP, *h216P;
    int *degP, *dstcP, *offP, *curP, *esrcP;
    cudaGetSymbolAddress((void**)&h16P,  g_h16);
    cudaGetSymbolAddress((void**)&wttP,  g_WtT);
    cudaGetSymbolAddress((void**)&bt1P,  g_BT1);
    cudaGetSymbolAddress((void**)&bt0P,  g_BT0);
    cudaGetSymbolAddress((void**)&bt2gP, g_BT2g);
    cudaGetSymbolAddress((void**)&bt2hP, g_BT2h);
    cudaGetSymbolAddress((void**)&g1P,   g_g1);
    cudaGetSymbolAddress((void**)&hwP,   g_hw);
    cudaGetSymbolAddress((void**)&s1P,   g_s1);
    cudaGetSymbolAddress((void**)&h216P, g_h216);
    cudaGetSymbolAddress((void**)&g2P,   g_g2);
    cudaGetSymbolAddress((void**)&hw2P,  g_hw2);
    cudaGetSymbolAddress((void**)&s2P,   g_s2);
    cudaGetSymbolAddress((void**)&dinvP, g_dinv);
    cudaGetSymbolAddress((void**)&degP,  g_deg);
    cudaGetSymbolAddress((void**)&dstcP, g_dstc);
    cudaGetSymbolAddress((void**)&offP,  g_off);
    cudaGetSymbolAddress((void**)&curP,  g_cur);
    cudaGetSymbolAddress((void**)&esrcP, g_esrc);
    cudaGetSymbolAddress((void**)&ewP,   g_ew);

    // --- CSR build (by dst) + dinv ---
    zero_cnt_kernel<<<(NNODE + 255) / 256, 256>>>(degP, dstcP);
    cnt_kernel<<<(NEDGE + 255) / 256, 256>>>(src, dst, degP, dstcP);
    dinv_kernel<<<(NNODE + 255) / 256, 256>>>(degP, dinvP);
    scan_kernel<<<1, 1024>>>(dstcP, offP, curP);
    fill_kernel<<<(NEDGE + 255) / 256, 256>>>(src, dst, dinvP, curP, esrcP, ewP);

    // --- weight prep (fp16) ---
    {
        dim3 grid((NNODE + 31) / 32, INC / 32);
        transpose_wt_kernel<<<grid, dim3(32, 8)>>>(Wt, wttP);
    }
    wconv_kernel<<<(INC * HID + 255) / 256, 256>>>(W1_1, bt1P, INC, HID, 0);
    wconv_kernel<<<(INC * HID + 255) / 256, 256>>>(W0_1, bt0P, INC, HID, 0);
    wconv_kernel<<<(HID * OUTC + 255) / 256, 256>>>(W1_mu, bt2gP, HID, OUTC, 0);
    wconv_kernel<<<(HID * OUTC + 255) / 256, 256>>>(W1_ls, bt2gP, HID, OUTC, OUTC);
    wconv_kernel<<<(HID * OUTC + 255) / 256, 256>>>(W0_mu, bt2hP, HID, OUTC, 0);
    wconv_kernel<<<(HID * OUTC + 255) / 256, 256>>>(W0_ls, bt2hP, HID, OUTC, OUTC);

    // --- h16 = relu(x @ Wt + bt) via mma.sync fp16 ---
    {
        cudaFuncSetAttribute(gemm_big_mma,
                             cudaFuncAttributeMaxDynamicSharedMemorySize, GSMEM_TOTAL);
        gemm_big_mma<<<NNODE / BM, 128, GSMEM_TOTAL>>>(x, wttP, bt, h16P);
    }
    // --- g1 = h@W1_1 ; hw = h@W0_1  (mma) ---
    sgemm_mma<INC><<<dim3(NNODE / SBM, 2), 128>>>(h16P, bt1P, bt0P, g1P, hwP);
    // --- s1 = gather(w * g1[src]) ---
    gather_kernel<<<(NNODE + 7) / 8, 256>>>(offP, esrcP, ewP, g1P, s1P);
    // --- h2 = relu(hw + s1 + b1) -> fp16 ---
    h2_ep_kernel<<<(NNODE * 32 + 255) / 256, 256>>>(hwP, s1P, b1, h216P);
    // --- g2 = h2@[W1mu|W1ls] ; hw2 = h2@[W0mu|W0ls]  (mma) ---
    sgemm_mma<HID><<<dim3(NNODE / SBM, 2), 128>>>(h216P, bt2gP, bt2hP, g2P, hw2P);
    // --- s2 = gather(w * g2[src]) ---
    gather_kernel<<<(NNODE + 7) / 8, 256>>>(offP, esrcP, ewP, g2P, s2P);
    // --- out = [hw2_mu + s2_mu + b_mu | hw2_ls + s2_ls + b_ls] ---
    out_ep_kernel<<<(NNODE * 16 + 255) / 256, 256>>>(hw2P, s2P, b_mu, b_ls, out);
}

// round 13
// speedup vs baseline: 4.2737x; 1.2652x over previous
#include <cuda_runtime.h>
#include <cuda_fp16.h>
#include <cstdint>

#define NNODE 10000
#define INC   256
#define HID   128      // 2*OUT_C
#define OUTC  64
#define NEDGE 640000

// ---- big GEMM tiling (mma.sync fp16, m16n8k16) ----
#define BM 80
#define BK 16
#define NKT (NNODE / BK)          // 625
#define A_BYTES (BM * BK * 2)     // 2560 (fp16)
#define B_BYTES (INC * BK * 2)    // 8192 (fp16)
#define STAGE_BYTES (A_BYTES + B_BYTES)     // 10752
#define NSTAGE 4
#define GSMEM_TOTAL (NSTAGE * STAGE_BYTES)  // 43008

// ---- small GEMM tiling ----
#define SBM 80
#define SBN 128
#define SA_BYTES (SBM * 16 * 2)            // 2560
#define SB_BYTES (SBN * 16 * 2)            // 4096
#define SSTAGE (SA_BYTES + SB_BYTES)       // 6656

// ---------------- scratch (device globals; no allocations allowed) ----------
__device__ __half g_h16 [NNODE * INC];  // relu(x@Wt+bt) fp16
__device__ __half g_WtT [INC * NNODE];  // Wt transposed (K-major), fp16
__device__ __half g_BT1 [HID * INC];    // W1_1^T fp16  [n][k]
__device__ __half g_BT0 [HID * INC];    // W0_1^T fp16
__device__ __half g_BT2g[HID * HID];    // [W1_mu|W1_ls]^T fp16
__device__ __half g_BT2h[HID * HID];    // [W0_mu|W0_ls]^T fp16
__device__ float  g_g1 [NNODE * HID];   // h @ W1_1
__device__ float  g_hw [NNODE * HID];   // h @ W0_1
__device__ float  g_s1 [NNODE * HID];   // gather of w*g1[src]
__device__ __half g_h216[NNODE * HID];  // relu(hw + s1 + b1) fp16
__device__ float  g_g2 [NNODE * HID];   // [h2@W1_mu | h2@W1_ls]
__device__ float  g_hw2[NNODE * HID];   // [h2@W0_mu | h2@W0_ls]
__device__ float  g_s2 [NNODE * HID];   // gather of w*g2[src]
__device__ float  g_dinv[NNODE];
__device__ int    g_deg [NNODE];
__device__ int    g_dstc[NNODE];
__device__ int    g_off [NNODE + 1];
__device__ int    g_cur [NNODE];
__device__ int    g_esrc[NEDGE];
__device__ float  g_ew  [NEDGE];

// ======================= helpers ============================================
__device__ __forceinline__ uint32_t smem_u32(const void* p) {
    uint32_t a;
    asm("{ .reg .u64 t; cvta.to.shared.u64 t, %1; cvt.u32.u64 %0, t; }" : "=r"(a) : "l"(p));
    return a;
}
__device__ __forceinline__ void cp_async16(uint32_t dst, const void* src) {
    asm volatile("cp.async.cg.shared.global [%0], [%1], 16;" :: "r"(dst), "l"(src));
}
#define CP_COMMIT() asm volatile("cp.async.commit_group;" ::: "memory")
#define CP_WAIT2()  asm volatile("cp.async.wait_group 2;" ::: "memory")
#define CP_WAIT1()  asm volatile("cp.async.wait_group 1;" ::: "memory")

__device__ __forceinline__ void ldsm4(uint32_t& r0, uint32_t& r1, uint32_t& r2, uint32_t& r3,
                                      uint32_t addr) {
    asm volatile("ldmatrix.sync.aligned.m8n8.x4.shared.b16 {%0,%1,%2,%3}, [%4];"
                 : "=r"(r0), "=r"(r1), "=r"(r2), "=r"(r3) : "r"(addr));
}
__device__ __forceinline__ void mma_f16(float* c, uint32_t a0, uint32_t a1, uint32_t a2,
                                        uint32_t a3, uint32_t b0, uint32_t b1) {
    asm volatile("mma.sync.aligned.m16n8k16.row.col.f32.f16.f16.f32 "
                 "{%0,%1,%2,%3}, {%4,%5,%6,%7}, {%8,%9}, {%0,%1,%2,%3};"
                 : "+f"(c[0]), "+f"(c[1]), "+f"(c[2]), "+f"(c[3])
                 : "r"(a0), "r"(a1), "r"(a2), "r"(a3), "r"(b0), "r"(b1));
}

// ---------------- CSR build --------------------------------------------------
__global__ void zero_cnt_kernel(int* deg, int* dstc) {
    int i = blockIdx.x * blockDim.x + threadIdx.x;
    if (i < NNODE) { deg[i] = 0; dstc[i] = 0; }
}
__global__ void cnt_kernel(const int* __restrict__ src, const int* __restrict__ dst,
                           int* __restrict__ deg, int* __restrict__ dstc) {
    int e = blockIdx.x * blockDim.x + threadIdx.x;
    if (e < NEDGE) {
        atomicAdd(&deg[src[e]], 1);
        atomicAdd(&dstc[dst[e]], 1);
    }
}
__global__ void dinv_kernel(const int* __restrict__ deg, float* __restrict__ dinv) {
    int i = blockIdx.x * blockDim.x + threadIdx.x;
    if (i < NNODE) {
        int d = deg[i];
        dinv[i] = (d > 0) ? rsqrtf((float)d) : 0.f;
    }
}
// single-block exclusive scan (coalesced via smem staging)
__global__ __launch_bounds__(1024) void scan_kernel(
    const int* __restrict__ cnt, int* __restrict__ off, int* __restrict__ cursor)
{
    __shared__ int sbuf[NNODE];
    __shared__ int wsum[32];
    const int tid = threadIdx.x;
    const int lane = tid & 31, wid = tid >> 5;
    for (int i = tid; i < NNODE; i += 1024) sbuf[i] = cnt[i];
    __syncthreads();

    const int CH = (NNODE + 1023) / 1024;   // 10
    int base = tid * CH;
    int local[CH];
    int sum = 0;
#pragma unroll
    for (int j = 0; j < CH; j++) {
        int i = base + j;
        int v = (i < NNODE) ? sbuf[i] : 0;
        local[j] = sum;
        sum += v;
    }
    int inc = sum;
#pragma unroll
    for (int d = 1; d < 32; d <<= 1) {
        int v = __shfl_up_sync(0xffffffffu, inc, d);
        if (lane >= d) inc += v;
    }
    if (lane == 31) wsum[wid] = inc;
    __syncthreads();
    if (wid == 0) {
        int w = wsum[lane];
        int wi = w;
#pragma unroll
        for (int d = 1; d < 32; d <<= 1) {
            int v = __shfl_up_sync(0xffffffffu, wi, d);
            if (lane >= d) wi += v;
        }
        wsum[lane] = wi - w;
    }
    __syncthreads();
    int pre = wsum[wid] + (inc - sum);
#pragma unroll
    for (int j = 0; j < CH; j++) {
        int i = base + j;
        if (i < NNODE) sbuf[i] = pre + local[j];
    }
    __syncthreads();
    for (int i = tid; i < NNODE; i += 1024) {
        int o = sbuf[i];
        off[i] = o;
        cursor[i] = o;
    }
    if (tid == 1023) off[NNODE] = pre + sum;
}
__global__ void fill_kernel(const int* __restrict__ src, const int* __restrict__ dst,
                            const float* __restrict__ dinv, int* __restrict__ cursor,
                            int* __restrict__ esrc, float* __restrict__ ew) {
    int e = blockIdx.x * blockDim.x + threadIdx.x;
    if (e < NEDGE) {
        int s = src[e], d = dst[e];
        int pos = atomicAdd(&cursor[d], 1);
        esrc[pos] = s;
        ew[pos] = -dinv[s] * dinv[d];
    }
}

// ---------------- gather: S[d] = sum_e w_e * G[src_e], warp per node ---------
__global__ void gather_kernel(const int* __restrict__ off, const int* __restrict__ esrc,
                              const float* __restrict__ ew, const float* __restrict__ G,
                              float* __restrict__ S)
{
    int node = blockIdx.x * 8 + (threadIdx.x >> 5);
    int lane = threadIdx.x & 31;
    if (node >= NNODE) return;
    int beg = off[node], end = off[node + 1];
    const float4* G4 = (const float4*)G;
    float4 acc = make_float4(0.f, 0.f, 0.f, 0.f);
    for (int base = beg; base < end; base += 32) {
        int idx = base + lane;
        int   se = 0;
        float we = 0.f;
        if (idx < end) { se = __ldg(&esrc[idx]); we = __ldg(&ew[idx]); }
        int n = min(32, end - base);
        for (int j = 0; j < n; j++) {
            int   sj = __shfl_sync(0xffffffffu, se, j);
            float wj = __shfl_sync(0xffffffffu, we, j);
            float4 v = __ldg(&G4[sj * 32 + lane]);
            acc.x += wj * v.x; acc.y += wj * v.y;
            acc.z += wj * v.z; acc.w += wj * v.w;
        }
    }
    ((float4*)S)[node * 32 + lane] = acc;
}

// ---------------- Wt transpose -> fp16 K-major -------------------------------
__global__ void transpose_wt_kernel(const float* __restrict__ Wt, __half* __restrict__ WtT) {
    __shared__ float t[32][33];
    int kb = blockIdx.x * 32, nb = blockIdx.y * 32;
    int x = threadIdx.x, y = threadIdx.y;     // block (32, 8)
#pragma unroll
    for (int j = 0; j < 32; j += 8) {
        int k = kb + y + j;
        t[y + j][x] = (k < NNODE) ? Wt[(size_t)k * INC + nb + x] : 0.f;
    }
    __syncthreads();
#pragma unroll
    for (int j = 0; j < 32; j += 8) {
        int k = kb + x;
        int n = nb + y + j;
        if (k < NNODE) WtT[(size_t)n * NNODE + k] = __float2half_rn(t[x][y + j]);
    }
}

// ---------------- small weight transpose: BT[(n0+n)*K + k] = W[k*N + n] ------
__global__ void wconv_kernel(const float* __restrict__ W, __half* __restrict__ BT,
                             int K, int N, int n0) {
    int i = blockIdx.x * blockDim.x + threadIdx.x;
    if (i < K * N) {
        int k = i / N, n = i - k * N;
        BT[(size_t)(n0 + n) * K + k] = __float2half_rn(W[i]);
    }
}

// ---------------- big GEMM: h16 = relu(x @ Wt + bt) via mma.sync fp16 -------
// 256 threads (8 warps), warp tile 80(M) x 32(N). A prefetch distance = 2 iters.
extern __shared__ char g_dyn_smem[];

__global__ __launch_bounds__(256) void gemm_big_mma(
    const float* __restrict__ A, const __half* __restrict__ BT,
    const float* __restrict__ bias, __half* __restrict__ C)
{
    char* smem = g_dyn_smem;
    const uint32_t sbase = smem_u32(smem);
    const int tid  = threadIdx.x;
    const int lane = tid & 31;
    const int w    = tid >> 5;           // 0..7
    const int row0 = blockIdx.x * BM;

    float c[5][4][4];
#pragma unroll
    for (int i = 0; i < 5; i++)
#pragma unroll
        for (int j = 0; j < 4; j++)
#pragma unroll
            for (int q = 0; q < 4; q++) c[i][j][q] = 0.f;

    // A staging: 160 16B-chunks; thread tid<160 handles chunk tid (r=tid>>1, kc=tid&1)
    // double-buffered registers for 2-iteration prefetch distance
    float4 ra[2][2];

    const int a_r  = tid >> 1;
    const int a_kc = tid & 1;
    const bool a_own = (tid < 160);

    auto ldgA = [&](int buf, int k0) {
        if (a_own) {
            const float* p = A + (size_t)(row0 + a_r) * NNODE + k0 + a_kc * 8;
            ra[buf][0] = *(const float4*)p;
            ra[buf][1] = *(const float4*)(p + 4);
        }
    };
    auto stsA = [&](int buf, int stage) {
        if (a_own) {
            char* base = smem + stage * STAGE_BYTES;
            __half2 h0 = __floats2half2_rn(ra[buf][0].x, ra[buf][0].y);
            __half2 h1 = __floats2half2_rn(ra[buf][0].z, ra[buf][0].w);
            __half2 h2 = __floats2half2_rn(ra[buf][1].x, ra[buf][1].y);
            __half2 h3 = __floats2half2_rn(ra[buf][1].z, ra[buf][1].w);
            uint4 u;
            u.x = *(uint32_t*)&h0; u.y = *(uint32_t*)&h1;
            u.z = *(uint32_t*)&h2; u.w = *(uint32_t*)&h3;
            int s = a_kc ^ ((a_r >> 2) & 1);
            *(uint4*)(base + a_r * 32 + s * 16) = u;
        }
    };
    // B staging: 512 16B-chunks via cp.async, 2 per thread
    auto cpB = [&](int stage, int k0) {
        uint32_t base = sbase + stage * STAGE_BYTES + A_BYTES;
#pragma unroll
        for (int it = 0; it < 2; it++) {
            int i  = tid + it * 256;
            int n  = i >> 1;
            int kc = i & 1;
            int s  = kc ^ ((n >> 2) & 1);
            cp_async16(base + (uint32_t)(n * 32 + s * 16),
                       BT + (size_t)n * NNODE + k0 + kc * 8);
        }
    };

    const int a_row  = (lane & 7) + ((lane >> 3) & 1) * 8;
    const int a_c    = (lane >> 4) & 1;
    const int b_nl   = (lane & 7) + ((lane >> 4) & 1) * 8;
    const int b_c    = (lane >> 3) & 1;

    // ---- prologue ----
    cpB(0, 0);          CP_COMMIT();
    cpB(1, 1 * BK);     CP_COMMIT();
    cpB(2, 2 * BK);     CP_COMMIT();
    ldgA(0, 0);         stsA(0, 0);
    ldgA(0, 1 * BK);    stsA(0, 1);
    ldgA(0, 2 * BK);    stsA(0, 2);
    ldgA(0, 3 * BK);                 // for kt=0's stsA (stage 3)
    ldgA(1, 4 * BK);                 // for kt=1's stsA (stage 0)

    for (int kt = 0; kt < NKT; kt++) {
        CP_WAIT2();
        __syncthreads();

        const int kn = kt + 3;
        if (kn < NKT) {
            cpB(kn & 3, kn * BK);
            stsA(kt & 1, kn & 3);
        }
        CP_COMMIT();
        if (kt + 5 < NKT) ldgA(kt & 1, (kt + 5) * BK);   // 2-iter distance

        const uint32_t abase = sbase + (uint32_t)(kt & 3) * STAGE_BYTES;
        const uint32_t bbase = abase + A_BYTES;

        uint32_t bb[2][4];
#pragma unroll
        for (int np = 0; np < 2; np++) {
            int n = w * 32 + np * 16 + b_nl;
            int s = b_c ^ ((n >> 2) & 1);
            ldsm4(bb[np][0], bb[np][1], bb[np][2], bb[np][3],
                  bbase + (uint32_t)(n * 32 + s * 16));
        }
#pragma unroll
        for (int mf = 0; mf < 5; mf++) {
            int r = mf * 16 + a_row;
            int s = a_c ^ ((r >> 2) & 1);
            uint32_t a0, a1, a2, a3;
            ldsm4(a0, a1, a2, a3, abase + (uint32_t)(r * 32 + s * 16));
#pragma unroll
            for (int np = 0; np < 2; np++) {
                mma_f16(c[mf][np * 2],     a0, a1, a2, a3, bb[np][0], bb[np][1]);
                mma_f16(c[mf][np * 2 + 1], a0, a1, a2, a3, bb[np][2], bb[np][3]);
            }
        }
    }

    // epilogue: bias + relu -> fp16
    const int g = lane >> 2;
    const int t2 = (lane & 3) * 2;
#pragma unroll
    for (int mf = 0; mf < 5; mf++) {
        int r = row0 + mf * 16 + g;
#pragma unroll
        for (int nf = 0; nf < 4; nf++) {
            int col = w * 32 + nf * 8 + t2;
            float2 bb = *(const float2*)(bias + col);
            __half2 p0 = __floats2half2_rn(fmaxf(c[mf][nf][0] + bb.x, 0.f),
                                           fmaxf(c[mf][nf][1] + bb.y, 0.f));
            __half2 p1 = __floats2half2_rn(fmaxf(c[mf][nf][2] + bb.x, 0.f),
                                           fmaxf(c[mf][nf][3] + bb.y, 0.f));
            *(__half2*)(C + (size_t)r * INC + col)       = p0;
            *(__half2*)(C + (size_t)(r + 8) * INC + col) = p1;
        }
    }
}

// ---------------- small GEMM via mma.sync fp16 -------------------------------
// C[by][10000 x 128] = A[10000 x KK] @ BT[by][128 x KK]^T ; all fp16 in, f32 out.
template<int KK>
__global__ __launch_bounds__(128) void sgemm_mma(
    const __half* __restrict__ A,
    const __half* __restrict__ BTa, const __half* __restrict__ BTb,
    float* __restrict__ Ca, float* __restrict__ Cb)
{
    __shared__ char smem[3 * SSTAGE];
    const uint32_t sbase = smem_u32(smem);
    const int tid  = threadIdx.x;
    const int lane = tid & 31;
    const int w    = tid >> 5;
    const int row0 = blockIdx.x * SBM;
    const __half* BT = blockIdx.y ? BTb : BTa;
    float* C = blockIdx.y ? Cb : Ca;
    const int SNKT = KK / 16;

    float c[5][4][4];
#pragma unroll
    for (int i = 0; i < 5; i++)
#pragma unroll
        for (int j = 0; j < 4; j++)
#pragma unroll
            for (int q = 0; q < 4; q++) c[i][j][q] = 0.f;

    auto ld_stage = [&](int stage, int kt) {
        uint32_t abase = sbase + (uint32_t)stage * SSTAGE;
        uint32_t bbase = abase + SA_BYTES;
        int k0 = kt * 16;
#pragma unroll
        for (int it = 0; it < 4; it++) {
            int i = tid + it * 128;
            if (i < 160) {
                int r = i >> 1, kc = i & 1;
                int s = kc ^ ((r >> 2) & 1);
                cp_async16(abase + (uint32_t)(r * 32 + s * 16),
                           A + (size_t)(row0 + r) * KK + k0 + kc * 8);
            } else if (i < 416) {
                int j = i - 160;
                int n = j >> 1, kc = j & 1;
                int s = kc ^ ((n >> 2) & 1);
                cp_async16(bbase + (uint32_t)(n * 32 + s * 16),
                           BT + (size_t)n * KK + k0 + kc * 8);
            }
        }
    };

    const int a_row  = (lane & 7) + ((lane >> 3) & 1) * 8;
    const int a_c    = (lane >> 4) & 1;
    const int b_nl   = (lane & 7) + ((lane >> 4) & 1) * 8;
    const int b_c    = (lane >> 3) & 1;

    ld_stage(0, 0); CP_COMMIT();
    ld_stage(1, 1); CP_COMMIT();

    for (int kt = 0; kt < SNKT; kt++) {
        CP_WAIT1();
        __syncthreads();
        if (kt + 2 < SNKT) ld_stage((kt + 2) % 3, kt + 2);
        CP_COMMIT();

        const uint32_t abase = sbase + (uint32_t)(kt % 3) * SSTAGE;
        const uint32_t bbase = abase + SA_BYTES;

        uint32_t bb[2][4];
#pragma unroll
        for (int np = 0; np < 2; np++) {
            int n = w * 32 + np * 16 + b_nl;
            int s = b_c ^ ((n >> 2) & 1);
            ldsm4(bb[np][0], bb[np][1], bb[np][2], bb[np][3],
                  bbase + (uint32_t)(n * 32 + s * 16));
        }
#pragma unroll
        for (int mf = 0; mf < 5; mf++) {
            int r = mf * 16 + a_row;
            int s = a_c ^ ((r >> 2) & 1);
            uint32_t a0, a1, a2, a3;
            ldsm4(a0, a1, a2, a3, abase + (uint32_t)(r * 32 + s * 16));
#pragma unroll
            for (int np = 0; np < 2; np++) {
                mma_f16(c[mf][np * 2],     a0, a1, a2, a3, bb[np][0], bb[np][1]);
                mma_f16(c[mf][np * 2 + 1], a0, a1, a2, a3, bb[np][2], bb[np][3]);
            }
        }
    }

    const int g = lane >> 2;
    const int t2 = (lane & 3) * 2;
#pragma unroll
    for (int mf = 0; mf < 5; mf++) {
        int r = row0 + mf * 16 + g;
#pragma unroll
        for (int nf = 0; nf < 4; nf++) {
            int col = w * 32 + nf * 8 + t2;
            float2 o0 = make_float2(c[mf][nf][0], c[mf][nf][1]);
            float2 o1 = make_float2(c[mf][nf][2], c[mf][nf][3]);
            *(float2*)(C + (size_t)r * HID + col)       = o0;
            *(float2*)(C + (size_t)(r + 8) * HID + col) = o1;
        }
    }
}

// ---------------- elementwise epilogues -------------------------------------
__global__ void h2_ep_kernel(const float* __restrict__ HW, const float* __restrict__ S1,
                             const float* __restrict__ b1, __half* __restrict__ H2)
{
    int i = blockIdx.x * blockDim.x + threadIdx.x;   // float4 index
    if (i >= NNODE * 32) return;
    int c4 = i & 31;
    float4 h = ((const float4*)HW)[i];
    float4 s = ((const float4*)S1)[i];
    float4 b = ((const float4*)b1)[c4];
    __half2 p0 = __floats2half2_rn(fmaxf(h.x + s.x + b.x, 0.f),
                                   fmaxf(h.y + s.y + b.y, 0.f));
    __half2 p1 = __floats2half2_rn(fmaxf(h.z + s.z + b.z, 0.f),
                                   fmaxf(h.w + s.w + b.w, 0.f));
    ((__half2*)H2)[i * 2]     = p0;
    ((__half2*)H2)[i * 2 + 1] = p1;
}

__global__ void out_ep_kernel(const float* __restrict__ HW2, const float* __restrict__ S2,
                              const float* __restrict__ bmu, const float* __restrict__ bls,
                              float* __restrict__ out)
{
    int i = blockIdx.x * blockDim.x + threadIdx.x;   // node*16 + c4
    if (i >= NNODE * 16) return;
    int n = i >> 4;
    int c4 = i & 15;
    float4 hm = ((const float4*)HW2)[n * 32 + c4];
    float4 sm = ((const float4*)S2)[n * 32 + c4];
    float4 bm = ((const float4*)bmu)[c4];
    float4 hl = ((const float4*)HW2)[n * 32 + 16 + c4];
    float4 sl = ((const float4*)S2)[n * 32 + 16 + c4];
    float4 bl = ((const float4*)bls)[c4];
    float4 om, ol;
    om.x = hm.x + sm.x + bm.x; om.y = hm.y + sm.y + bm.y;
    om.z = hm.z + sm.z + bm.z; om.w = hm.w + sm.w + bm.w;
    ol.x = hl.x + sl.x + bl.x; ol.y = hl.y + sl.y + bl.y;
    ol.z = hl.z + sl.z + bl.z; ol.w = hl.w + sl.w + bl.w;
    ((float4*)out)[n * 16 + c4] = om;
    ((float4*)out)[NNODE * 16 + n * 16 + c4] = ol;
}

// ---------------- launch -----------------------------------------------------
extern "C" void kernel_launch(void* const* d_in, const int* in_sizes, int n_in,
                              void* d_out, int out_size)
{
    const float* x     = (const float*)d_in[0];
    const int*   ei    = (const int*)  d_in[1];
    const float* Wt    = (const float*)d_in[2];
    const float* bt    = (const float*)d_in[3];
    const float* W0_1  = (const float*)d_in[4];
    const float* W1_1  = (const float*)d_in[5];
    const float* b1    = (const float*)d_in[6];
    const float* W0_mu = (const float*)d_in[7];
    const float* W1_mu = (const float*)d_in[8];
    const float* b_mu  = (const float*)d_in[9];
    const float* W0_ls = (const float*)d_in[10];
    const float* W1_ls = (const float*)d_in[11];
    const float* b_ls  = (const float*)d_in[12];
    float* out = (float*)d_out;

    const int* src = ei;
    const int* dst = ei + NEDGE;

    float *g1P, *hwP, *s1P, *g2P, *hw2P, *s2P, *dinvP, *ewP;
    __half *h16P, *wttP, *bt1P, *bt0P, *bt2gP, *bt2hP, *h216P;
    int *degP, *dstcP, *offP, *curP, *esrcP;
    cudaGetSymbolAddress((void**)&h16P,  g_h16);
    cudaGetSymbolAddress((void**)&wttP,  g_WtT);
    cudaGetSymbolAddress((void**)&bt1P,  g_BT1);
    cudaGetSymbolAddress((void**)&bt0P,  g_BT0);
    cudaGetSymbolAddress((void**)&bt2gP, g_BT2g);
    cudaGetSymbolAddress((void**)&bt2hP, g_BT2h);
    cudaGetSymbolAddress((void**)&g1P,   g_g1);
    cudaGetSymbolAddress((void**)&hwP,   g_hw);
    cudaGetSymbolAddress((void**)&s1P,   g_s1);
    cudaGetSymbolAddress((void**)&h216P, g_h216);
    cudaGetSymbolAddress((void**)&g2P,   g_g2);
    cudaGetSymbolAddress((void**)&hw2P,  g_hw2);
    cudaGetSymbolAddress((void**)&s2P,   g_s2);
    cudaGetSymbolAddress((void**)&dinvP, g_dinv);
    cudaGetSymbolAddress((void**)&degP,  g_deg);
    cudaGetSymbolAddress((void**)&dstcP, g_dstc);
    cudaGetSymbolAddress((void**)&offP,  g_off);
    cudaGetSymbolAddress((void**)&curP,  g_cur);
    cudaGetSymbolAddress((void**)&esrcP, g_esrc);
    cudaGetSymbolAddress((void**)&ewP,   g_ew);

    // --- CSR build (by dst) + dinv ---
    zero_cnt_kernel<<<(NNODE + 255) / 256, 256>>>(degP, dstcP);
    cnt_kernel<<<(NEDGE + 255) / 256, 256>>>(src, dst, degP, dstcP);
    dinv_kernel<<<(NNODE + 255) / 256, 256>>>(degP, dinvP);
    scan_kernel<<<1, 1024>>>(dstcP, offP, curP);
    fill_kernel<<<(NEDGE + 255) / 256, 256>>>(src, dst, dinvP, curP, esrcP, ewP);

    // --- weight prep (fp16) ---
    {
        dim3 grid((NNODE + 31) / 32, INC / 32);
        transpose_wt_kernel<<<grid, dim3(32, 8)>>>(Wt, wttP);
    }
    wconv_kernel<<<(INC * HID + 255) / 256, 256>>>(W1_1, bt1P, INC, HID, 0);
    wconv_kernel<<<(INC * HID + 255) / 256, 256>>>(W0_1, bt0P, INC, HID, 0);
    wconv_kernel<<<(HID * OUTC + 255) / 256, 256>>>(W1_mu, bt2gP, HID, OUTC, 0);
    wconv_kernel<<<(HID * OUTC + 255) / 256, 256>>>(W1_ls, bt2gP, HID, OUTC, OUTC);
    wconv_kernel<<<(HID * OUTC + 255) / 256, 256>>>(W0_mu, bt2hP, HID, OUTC, 0);
    wconv_kernel<<<(HID * OUTC + 255) / 256, 256>>>(W0_ls, bt2hP, HID, OUTC, OUTC);

    // --- h16 = relu(x @ Wt + bt) via mma.sync fp16 (256 thr) ---
    {
        cudaFuncSetAttribute(gemm_big_mma,
                             cudaFuncAttributeMaxDynamicSharedMemorySize, GSMEM_TOTAL);
        gemm_big_mma<<<NNODE / BM, 256, GSMEM_TOTAL>>>(x, wttP, bt, h16P);
    }
    // --- g1 = h@W1_1 ; hw = h@W0_1  (mma) ---
    sgemm_mma<INC><<<dim3(NNODE / SBM, 2), 128>>>(h16P, bt1P, bt0P, g1P, hwP);
    // --- s1 = gather(w * g1[src]) ---
    gather_kernel<<<(NNODE + 7) / 8, 256>>>(offP, esrcP, ewP, g1P, s1P);
    // --- h2 = relu(hw + s1 + b1) -> fp16 ---
    h2_ep_kernel<<<(NNODE * 32 + 255) / 256, 256>>>(hwP, s1P, b1, h216P);
    // --- g2 = h2@[W1mu|W1ls] ; hw2 = h2@[W0mu|W0ls]  (mma) ---
    sgemm_mma<HID><<<dim3(NNODE / SBM, 2), 128>>>(h216P, bt2gP, bt2hP, g2P, hw2P);
    // --- s2 = gather(w * g2[src]) ---
    gather_kernel<<<(NNODE + 7) / 8, 256>>>(offP, esrcP, ewP, g2P, s2P);
    // --- out = [hw2_mu + s2_mu + b_mu | hw2_ls + s2_ls + b_ls] ---
    out_ep_kernel<<<(NNODE * 16 + 255) / 256, 256>>>(hw2P, s2P, b_mu, b_ls, out);
}

// round 14
// speedup vs baseline: 5.3559x; 1.2532x over previous
#include <cuda_runtime.h>
#include <cuda_fp16.h>
#include <cstdint>

#define NNODE 10000
#define KPAD  10016     // padded K stride for WtT (pad bytes never written -> zero)
#define INC   256
#define HID   128      // 2*OUT_C
#define OUTC  64
#define NEDGE 640000

// ---- big GEMM tiling (mma.sync fp16, m16n8k16, BK=32) ----
#define BM 80
#define BK 32
#define NKT ((NNODE + BK - 1) / BK)   // 313 (last iter: 16 valid k, rest zero-padded)
#define A_BYTES (BM * BK * 2)     // 5120 (fp16)
#define B_BYTES (INC * BK * 2)    // 16384 (fp16)
#define STAGE_BYTES (A_BYTES + B_BYTES)     // 21504
#define NSTAGE 4
#define GSMEM_TOTAL (NSTAGE * STAGE_BYTES)  // 86016

// ---- small GEMM tiling ----
#define SBM 80
#define SBN 128
#define SA_BYTES (SBM * 16 * 2)            // 2560
#define SB_BYTES (SBN * 16 * 2)            // 4096
#define SSTAGE (SA_BYTES + SB_BYTES)       // 6656

// ---------------- scratch (device globals; no allocations allowed) ----------
__device__ __half g_h16 [NNODE * INC];  // relu(x@Wt+bt) fp16
__device__ __half g_WtT [INC * KPAD];   // Wt transposed (K-major, padded), fp16
__device__ __half g_BT1 [HID * INC];    // W1_1^T fp16  [n][k]
__device__ __half g_BT0 [HID * INC];    // W0_1^T fp16
__device__ __half g_BT2g[HID * HID];    // [W1_mu|W1_ls]^T fp16
__device__ __half g_BT2h[HID * HID];    // [W0_mu|W0_ls]^T fp16
__device__ float  g_g1 [NNODE * HID];   // h @ W1_1
__device__ float  g_hw [NNODE * HID];   // h @ W0_1
__device__ __half g_h216[NNODE * HID];  // relu(hw + s1 + b1) fp16
__device__ float  g_g2 [NNODE * HID];   // [h2@W1_mu | h2@W1_ls]
__device__ float  g_hw2[NNODE * HID];   // [h2@W0_mu | h2@W0_ls]
__device__ float  g_dinv[NNODE];
__device__ int    g_deg [NNODE];
__device__ int    g_dstc[NNODE];
__device__ int    g_off [NNODE + 1];
__device__ int    g_cur [NNODE];
__device__ int    g_esrc[NEDGE];
__device__ float  g_ew  [NEDGE];

// ======================= helpers ============================================
__device__ __forceinline__ uint32_t smem_u32(const void* p) {
    uint32_t a;
    asm("{ .reg .u64 t; cvta.to.shared.u64 t, %1; cvt.u32.u64 %0, t; }" : "=r"(a) : "l"(p));
    return a;
}
__device__ __forceinline__ void cp_async16(uint32_t dst, const void* src) {
    asm volatile("cp.async.cg.shared.global [%0], [%1], 16;" :: "r"(dst), "l"(src));
}
#define CP_COMMIT() asm volatile("cp.async.commit_group;" ::: "memory")
#define CP_WAIT2()  asm volatile("cp.async.wait_group 2;" ::: "memory")
#define CP_WAIT1()  asm volatile("cp.async.wait_group 1;" ::: "memory")

__device__ __forceinline__ void ldsm4(uint32_t& r0, uint32_t& r1, uint32_t& r2, uint32_t& r3,
                                      uint32_t addr) {
    asm volatile("ldmatrix.sync.aligned.m8n8.x4.shared.b16 {%0,%1,%2,%3}, [%4];"
                 : "=r"(r0), "=r"(r1), "=r"(r2), "=r"(r3) : "r"(addr));
}
__device__ __forceinline__ void mma_f16(float* c, uint32_t a0, uint32_t a1, uint32_t a2,
                                        uint32_t a3, uint32_t b0, uint32_t b1) {
    asm volatile("mma.sync.aligned.m16n8k16.row.col.f32.f16.f16.f32 "
                 "{%0,%1,%2,%3}, {%4,%5,%6,%7}, {%8,%9}, {%0,%1,%2,%3};"
                 : "+f"(c[0]), "+f"(c[1]), "+f"(c[2]), "+f"(c[3])
                 : "r"(a0), "r"(a1), "r"(a2), "r"(a3), "r"(b0), "r"(b1));
}

// ---------------- CSR build --------------------------------------------------
__global__ void zero_cnt_kernel(int* deg, int* dstc) {
    int i = blockIdx.x * blockDim.x + threadIdx.x;
    if (i < NNODE) { deg[i] = 0; dstc[i] = 0; }
}
__global__ void cnt_kernel(const int* __restrict__ src, const int* __restrict__ dst,
                           int* __restrict__ deg, int* __restrict__ dstc) {
    int e = blockIdx.x * blockDim.x + threadIdx.x;
    if (e < NEDGE) {
        atomicAdd(&deg[src[e]], 1);
        atomicAdd(&dstc[dst[e]], 1);
    }
}
__global__ void dinv_kernel(const int* __restrict__ deg, float* __restrict__ dinv) {
    int i = blockIdx.x * blockDim.x + threadIdx.x;
    if (i < NNODE) {
        int d = deg[i];
        dinv[i] = (d > 0) ? rsqrtf((float)d) : 0.f;
    }
}
// single-block exclusive scan (coalesced via smem staging)
__global__ __launch_bounds__(1024) void scan_kernel(
    const int* __restrict__ cnt, int* __restrict__ off, int* __restrict__ cursor)
{
    __shared__ int sbuf[NNODE];
    __shared__ int wsum[32];
    const int tid = threadIdx.x;
    const int lane = tid & 31, wid = tid >> 5;
    for (int i = tid; i < NNODE; i += 1024) sbuf[i] = cnt[i];
    __syncthreads();

    const int CH = (NNODE + 1023) / 1024;   // 10
    int base = tid * CH;
    int local[CH];
    int sum = 0;
#pragma unroll
    for (int j = 0; j < CH; j++) {
        int i = base + j;
        int v = (i < NNODE) ? sbuf[i] : 0;
        local[j] = sum;
        sum += v;
    }
    int inc = sum;
#pragma unroll
    for (int d = 1; d < 32; d <<= 1) {
        int v = __shfl_up_sync(0xffffffffu, inc, d);
        if (lane >= d) inc += v;
    }
    if (lane == 31) wsum[wid] = inc;
    __syncthreads();
    if (wid == 0) {
        int w = wsum[lane];
        int wi = w;
#pragma unroll
        for (int d = 1; d < 32; d <<= 1) {
            int v = __shfl_up_sync(0xffffffffu, wi, d);
            if (lane >= d) wi += v;
        }
        wsum[lane] = wi - w;
    }
    __syncthreads();
    int pre = wsum[wid] + (inc - sum);
#pragma unroll
    for (int j = 0; j < CH; j++) {
        int i = base + j;
        if (i < NNODE) sbuf[i] = pre + local[j];
    }
    __syncthreads();
    for (int i = tid; i < NNODE; i += 1024) {
        int o = sbuf[i];
        off[i] = o;
        cursor[i] = o;
    }
    if (tid == 1023) off[NNODE] = pre + sum;
}
__global__ void fill_kernel(const int* __restrict__ src, const int* __restrict__ dst,
                            const float* __restrict__ dinv, int* __restrict__ cursor,
                            int* __restrict__ esrc, float* __restrict__ ew) {
    int e = blockIdx.x * blockDim.x + threadIdx.x;
    if (e < NEDGE) {
        int s = src[e], d = dst[e];
        int pos = atomicAdd(&cursor[d], 1);
        esrc[pos] = s;
        ew[pos] = -dinv[s] * dinv[d];
    }
}

// ---------------- fused gather #1: h2 = relu(hw + gather(w*g1) + b1) -> fp16 -
__global__ void gather_h2_kernel(const int* __restrict__ off, const int* __restrict__ esrc,
                                 const float* __restrict__ ew, const float* __restrict__ G,
                                 const float* __restrict__ HW, const float* __restrict__ b1,
                                 __half* __restrict__ H2)
{
    int node = blockIdx.x * 8 + (threadIdx.x >> 5);
    int lane = threadIdx.x & 31;
    if (node >= NNODE) return;
    int beg = off[node], end = off[node + 1];
    const float4* G4 = (const float4*)G;
    float4 acc = make_float4(0.f, 0.f, 0.f, 0.f);
    for (int base = beg; base < end; base += 32) {
        int idx = base + lane;
        int   se = 0;
        float we = 0.f;
        if (idx < end) { se = __ldg(&esrc[idx]); we = __ldg(&ew[idx]); }
        int n = min(32, end - base);
        for (int j = 0; j < n; j++) {
            int   sj = __shfl_sync(0xffffffffu, se, j);
            float wj = __shfl_sync(0xffffffffu, we, j);
            float4 v = __ldg(&G4[sj * 32 + lane]);
            acc.x += wj * v.x; acc.y += wj * v.y;
            acc.z += wj * v.z; acc.w += wj * v.w;
        }
    }
    float4 h = ((const float4*)HW)[node * 32 + lane];
    float4 b = ((const float4*)b1)[lane];
    __half2 p0 = __floats2half2_rn(fmaxf(acc.x + h.x + b.x, 0.f),
                                   fmaxf(acc.y + h.y + b.y, 0.f));
    __half2 p1 = __floats2half2_rn(fmaxf(acc.z + h.z + b.z, 0.f),
                                   fmaxf(acc.w + h.w + b.w, 0.f));
    uint2 u;
    u.x = *(uint32_t*)&p0; u.y = *(uint32_t*)&p1;
    ((uint2*)H2)[node * 32 + lane] = u;
}

// ---------------- fused gather #2: out = hw2 + gather(w*g2) + bias ----------
__global__ void gather_out_kernel(const int* __restrict__ off, const int* __restrict__ esrc,
                                  const float* __restrict__ ew, const float* __restrict__ G,
                                  const float* __restrict__ HW2,
                                  const float* __restrict__ bmu, const float* __restrict__ bls,
                                  float* __restrict__ out)
{
    int node = blockIdx.x * 8 + (threadIdx.x >> 5);
    int lane = threadIdx.x & 31;
    if (node >= NNODE) return;
    int beg = off[node], end = off[node + 1];
    const float4* G4 = (const float4*)G;
    float4 acc = make_float4(0.f, 0.f, 0.f, 0.f);
    for (int base = beg; base < end; base += 32) {
        int idx = base + lane;
        int   se = 0;
        float we = 0.f;
        if (idx < end) { se = __ldg(&esrc[idx]); we = __ldg(&ew[idx]); }
        int n = min(32, end - base);
        for (int j = 0; j < n; j++) {
            int   sj = __shfl_sync(0xffffffffu, se, j);
            float wj = __shfl_sync(0xffffffffu, we, j);
            float4 v = __ldg(&G4[sj * 32 + lane]);
            acc.x += wj * v.x; acc.y += wj * v.y;
            acc.z += wj * v.z; acc.w += wj * v.w;
        }
    }
    float4 h = ((const float4*)HW2)[node * 32 + lane];
    int hf = lane >> 4;          // 0 = mu cols, 1 = logstd cols
    int c4 = lane & 15;
    const float4* bp = hf ? (const float4*)bls : (const float4*)bmu;
    float4 b = bp[c4];
    float4 o;
    o.x = acc.x + h.x + b.x; o.y = acc.y + h.y + b.y;
    o.z = acc.z + h.z + b.z; o.w = acc.w + h.w + b.w;
    ((float4*)(out + (size_t)hf * NNODE * OUTC))[node * 16 + c4] = o;
}

// ---------------- Wt transpose -> fp16 K-major (padded stride) ---------------
__global__ void transpose_wt_kernel(const float* __restrict__ Wt, __half* __restrict__ WtT) {
    __shared__ float t[32][33];
    int kb = blockIdx.x * 32, nb = blockIdx.y * 32;
    int x = threadIdx.x, y = threadIdx.y;     // block (32, 8)
#pragma unroll
    for (int j = 0; j < 32; j += 8) {
        int k = kb + y + j;
        t[y + j][x] = (k < NNODE) ? Wt[(size_t)k * INC + nb + x] : 0.f;
    }
    __syncthreads();
#pragma unroll
    for (int j = 0; j < 32; j += 8) {
        int k = kb + x;
        int n = nb + y + j;
        if (k < NNODE) WtT[(size_t)n * KPAD + k] = __float2half_rn(t[x][y + j]);
    }
}

// ---------------- small weight transpose: BT[(n0+n)*K + k] = W[k*N + n] ------
__global__ void wconv_kernel(const float* __restrict__ W, __half* __restrict__ BT,
                             int K, int N, int n0) {
    int i = blockIdx.x * blockDim.x + threadIdx.x;
    if (i < K * N) {
        int k = i / N, n = i - k * N;
        BT[(size_t)(n0 + n) * K + k] = __float2half_rn(W[i]);
    }
}

// ---------------- big GEMM: h16 = relu(x @ Wt + bt), BK=32, 256 threads -----
// smem rows: 64B (32 halfs); 16B unit c in {0..3} swizzled: c ^= (r>>1)&3.
extern __shared__ char g_dyn_smem[];

__global__ __launch_bounds__(256) void gemm_big_mma(
    const float* __restrict__ A, const __half* __restrict__ BT,
    const float* __restrict__ bias, __half* __restrict__ C)
{
    char* smem = g_dyn_smem;
    const uint32_t sbase = smem_u32(smem);
    const int tid  = threadIdx.x;
    const int lane = tid & 31;
    const int w    = tid >> 5;           // 0..7
    const int row0 = blockIdx.x * BM;

    float c[5][4][4];
#pragma unroll
    for (int i = 0; i < 5; i++)
#pragma unroll
        for (int j = 0; j < 4; j++)
#pragma unroll
            for (int q = 0; q < 4; q++) c[i][j][q] = 0.f;

    // A staging: 320 16B-fp16 chunks (r=c>>2, kc=c&3). Thread owns chunk tid,
    // and chunk 256+tid if tid<64. One register buffer (distance-1 prefetch,
    // one BK=32 compute phase ~ >600cyc > DRAM latency).
    float4 ra0[2], ra1[2];
    const int c0r = tid >> 2, c0k = tid & 3;
    const int c1  = 256 + tid;
    const int c1r = c1 >> 2, c1k = c1 & 3;
    const bool own1 = (tid < 64);

    auto ldgA = [&](int k0) {
        {
            int kk = k0 + c0k * 8;
            if (kk + 8 <= NNODE) {
                const float* p = A + (size_t)(row0 + c0r) * NNODE + kk;
                ra0[0] = *(const float4*)p;
                ra0[1] = *(const float4*)(p + 4);
            } else {
                ra0[0] = make_float4(0.f,0.f,0.f,0.f);
                ra0[1] = make_float4(0.f,0.f,0.f,0.f);
            }
        }
        if (own1) {
            int kk = k0 + c1k * 8;
            if (kk + 8 <= NNODE) {
                const float* p = A + (size_t)(row0 + c1r) * NNODE + kk;
                ra1[0] = *(const float4*)p;
                ra1[1] = *(const float4*)(p + 4);
            } else {
                ra1[0] = make_float4(0.f,0.f,0.f,0.f);
                ra1[1] = make_float4(0.f,0.f,0.f,0.f);
            }
        }
    };
    auto cvt16 = [](float4 v0, float4 v1) {
        __half2 h0 = __floats2half2_rn(v0.x, v0.y);
        __half2 h1 = __floats2half2_rn(v0.z, v0.w);
        __half2 h2 = __floats2half2_rn(v1.x, v1.y);
        __half2 h3 = __floats2half2_rn(v1.z, v1.w);
        uint4 u;
        u.x = *(uint32_t*)&h0; u.y = *(uint32_t*)&h1;
        u.z = *(uint32_t*)&h2; u.w = *(uint32_t*)&h3;
        return u;
    };
    auto stsA = [&](int stage) {
        char* base = smem + stage * STAGE_BYTES;
        {
            int s = c0k ^ ((c0r >> 1) & 3);
            *(uint4*)(base + c0r * 64 + s * 16) = cvt16(ra0[0], ra0[1]);
        }
        if (own1) {
            int s = c1k ^ ((c1r >> 1) & 3);
            *(uint4*)(base + c1r * 64 + s * 16) = cvt16(ra1[0], ra1[1]);
        }
    };
    // B staging: 1024 16B chunks via cp.async, 4 per thread (padded WtT, no guard)
    auto cpB = [&](int stage, int k0) {
        uint32_t base = sbase + stage * STAGE_BYTES + A_BYTES;
#pragma unroll
        for (int it = 0; it < 4; it++) {
            int i  = tid + it * 256;
            int n  = i >> 2;
            int kc = i & 3;
            int s  = kc ^ ((n >> 1) & 3);
            cp_async16(base + (uint32_t)(n * 64 + s * 16),
                       BT + (size_t)n * KPAD + k0 + kc * 8);
        }
    };

    const int a_row  = (lane & 7) + ((lane >> 3) & 1) * 8;
    const int a_c    = (lane >> 4) & 1;
    const int b_nl   = (lane & 7) + ((lane >> 4) & 1) * 8;
    const int b_c    = (lane >> 3) & 1;

    // ---- prologue ----
    cpB(0, 0);          CP_COMMIT();
    cpB(1, 1 * BK);     CP_COMMIT();
    cpB(2, 2 * BK);     CP_COMMIT();
    ldgA(0);            stsA(0);
    ldgA(1 * BK);       stsA(1);
    ldgA(2 * BK);       stsA(2);
    ldgA(3 * BK);                    // held for stage 3 (stored at kt=0)

    for (int kt = 0; kt < NKT; kt++) {
        CP_WAIT2();
        __syncthreads();

        const int kn = kt + 3;
        if (kn < NKT) {
            cpB(kn & 3, kn * BK);
            stsA(kn & 3);            // uses A data ldg'd last iteration (k = kn*BK)
        }
        CP_COMMIT();
        if (kt + 4 < NKT) ldgA((kt + 4) * BK);

        const uint32_t abase = sbase + (uint32_t)(kt & 3) * STAGE_BYTES;
        const uint32_t bbase = abase + A_BYTES;

#pragma unroll
        for (int ks = 0; ks < 2; ks++) {
            uint32_t bb[2][4];
#pragma unroll
            for (int np = 0; np < 2; np++) {
                int n = w * 32 + np * 16 + b_nl;
                int s = (ks * 2 + b_c) ^ ((n >> 1) & 3);
                ldsm4(bb[np][0], bb[np][1], bb[np][2], bb[np][3],
                      bbase + (uint32_t)(n * 64 + s * 16));
            }
#pragma unroll
            for (int mf = 0; mf < 5; mf++) {
                int r = mf * 16 + a_row;
                int s = (ks * 2 + a_c) ^ ((r >> 1) & 3);
                uint32_t a0, a1, a2, a3;
                ldsm4(a0, a1, a2, a3, abase + (uint32_t)(r * 64 + s * 16));
#pragma unroll
                for (int np = 0; np < 2; np++) {
                    mma_f16(c[mf][np * 2],     a0, a1, a2, a3, bb[np][0], bb[np][1]);
                    mma_f16(c[mf][np * 2 + 1], a0, a1, a2, a3, bb[np][2], bb[np][3]);
                }
            }
        }
    }

    // epilogue: bias + relu -> fp16
    const int g = lane >> 2;
    const int t2 = (lane & 3) * 2;
#pragma unroll
    for (int mf = 0; mf < 5; mf++) {
        int r = row0 + mf * 16 + g;
#pragma unroll
        for (int nf = 0; nf < 4; nf++) {
            int col = w * 32 + nf * 8 + t2;
            float2 bb = *(const float2*)(bias + col);
            __half2 p0 = __floats2half2_rn(fmaxf(c[mf][nf][0] + bb.x, 0.f),
                                           fmaxf(c[mf][nf][1] + bb.y, 0.f));
            __half2 p1 = __floats2half2_rn(fmaxf(c[mf][nf][2] + bb.x, 0.f),
                                           fmaxf(c[mf][nf][3] + bb.y, 0.f));
            *(__half2*)(C + (size_t)r * INC + col)       = p0;
            *(__half2*)(C + (size_t)(r + 8) * INC + col) = p1;
        }
    }
}

// ---------------- small GEMM via mma.sync fp16 -------------------------------
// C[by][10000 x 128] = A[10000 x KK] @ BT[by][128 x KK]^T ; all fp16 in, f32 out.
template<int KK>
__global__ __launch_bounds__(128) void sgemm_mma(
    const __half* __restrict__ A,
    const __half* __restrict__ BTa, const __half* __restrict__ BTb,
    float* __restrict__ Ca, float* __restrict__ Cb)
{
    __shared__ char smem[3 * SSTAGE];
    const uint32_t sbase = smem_u32(smem);
    const int tid  = threadIdx.x;
    const int lane = tid & 31;
    const int w    = tid >> 5;
    const int row0 = blockIdx.x * SBM;
    const __half* BT = blockIdx.y ? BTb : BTa;
    float* C = blockIdx.y ? Cb : Ca;
    const int SNKT = KK / 16;

    float c[5][4][4];
#pragma unroll
    for (int i = 0; i < 5; i++)
#pragma unroll
        for (int j = 0; j < 4; j++)
#pragma unroll
            for (int q = 0; q < 4; q++) c[i][j][q] = 0.f;

    auto ld_stage = [&](int stage, int kt) {
        uint32_t abase = sbase + (uint32_t)stage * SSTAGE;
        uint32_t bbase = abase + SA_BYTES;
        int k0 = kt * 16;
#pragma unroll
        for (int it = 0; it < 4; it++) {
            int i = tid + it * 128;
            if (i < 160) {
                int r = i >> 1, kc = i & 1;
                int s = kc ^ ((r >> 2) & 1);
                cp_async16(abase + (uint32_t)(r * 32 + s * 16),
                           A + (size_t)(row0 + r) * KK + k0 + kc * 8);
            } else if (i < 416) {
                int j = i - 160;
                int n = j >> 1, kc = j & 1;
                int s = kc ^ ((n >> 2) & 1);
                cp_async16(bbase + (uint32_t)(n * 32 + s * 16),
                           BT + (size_t)n * KK + k0 + kc * 8);
            }
        }
    };

    const int a_row  = (lane & 7) + ((lane >> 3) & 1) * 8;
    const int a_c    = (lane >> 4) & 1;
    const int b_nl   = (lane & 7) + ((lane >> 4) & 1) * 8;
    const int b_c    = (lane >> 3) & 1;

    ld_stage(0, 0); CP_COMMIT();
    ld_stage(1, 1); CP_COMMIT();

    for (int kt = 0; kt < SNKT; kt++) {
        CP_WAIT1();
        __syncthreads();
        if (kt + 2 < SNKT) ld_stage((kt + 2) % 3, kt + 2);
        CP_COMMIT();

        const uint32_t abase = sbase + (uint32_t)(kt % 3) * SSTAGE;
        const uint32_t bbase = abase + SA_BYTES;

        uint32_t bb[2][4];
#pragma unroll
        for (int np = 0; np < 2; np++) {
            int n = w * 32 + np * 16 + b_nl;
            int s = b_c ^ ((n >> 2) & 1);
            ldsm4(bb[np][0], bb[np][1], bb[np][2], bb[np][3],
                  bbase + (uint32_t)(n * 32 + s * 16));
        }
#pragma unroll
        for (int mf = 0; mf < 5; mf++) {
            int r = mf * 16 + a_row;
            int s = a_c ^ ((r >> 2) & 1);
            uint32_t a0, a1, a2, a3;
            ldsm4(a0, a1, a2, a3, abase + (uint32_t)(r * 32 + s * 16));
#pragma unroll
            for (int np = 0; np < 2; np++) {
                mma_f16(c[mf][np * 2],     a0, a1, a2, a3, bb[np][0], bb[np][1]);
                mma_f16(c[mf][np * 2 + 1], a0, a1, a2, a3, bb[np][2], bb[np][3]);
            }
        }
    }

    const int g = lane >> 2;
    const int t2 = (lane & 3) * 2;
#pragma unroll
    for (int mf = 0; mf < 5; mf++) {
        int r = row0 + mf * 16 + g;
#pragma unroll
        for (int nf = 0; nf < 4; nf++) {
            int col = w * 32 + nf * 8 + t2;
            float2 o0 = make_float2(c[mf][nf][0], c[mf][nf][1]);
            float2 o1 = make_float2(c[mf][nf][2], c[mf][nf][3]);
            *(float2*)(C + (size_t)r * HID + col)       = o0;
            *(float2*)(C + (size_t)(r + 8) * HID + col) = o1;
        }
    }
}

// ---------------- launch -----------------------------------------------------
extern "C" void kernel_launch(void* const* d_in, const int* in_sizes, int n_in,
                              void* d_out, int out_size)
{
    const float* x     = (const float*)d_in[0];
    const int*   ei    = (const int*)  d_in[1];
    const float* Wt    = (const float*)d_in[2];
    const float* bt    = (const float*)d_in[3];
    const float* W0_1  = (const float*)d_in[4];
    const float* W1_1  = (const float*)d_in[5];
    const float* b1    = (const float*)d_in[6];
    const float* W0_mu = (const float*)d_in[7];
    const float* W1_mu = (const float*)d_in[8];
    const float* b_mu  = (const float*)d_in[9];
    const float* W0_ls = (const float*)d_in[10];
    const float* W1_ls = (const float*)d_in[11];
    const float* b_ls  = (const float*)d_in[12];
    float* out = (float*)d_out;

    const int* src = ei;
    const int* dst = ei + NEDGE;

    float *g1P, *hwP, *g2P, *hw2P, *dinvP, *ewP;
    __half *h16P, *wttP, *bt1P, *bt0P, *bt2gP, *bt2hP, *h216P;
    int *degP, *dstcP, *offP, *curP, *esrcP;
    cudaGetSymbolAddress((void**)&h16P,  g_h16);
    cudaGetSymbolAddress((void**)&wttP,  g_WtT);
    cudaGetSymbolAddress((void**)&bt1P,  g_BT1);
    cudaGetSymbolAddress((void**)&bt0P,  g_BT0);
    cudaGetSymbolAddress((void**)&bt2gP, g_BT2g);
    cudaGetSymbolAddress((void**)&bt2hP, g_BT2h);
    cudaGetSymbolAddress((void**)&g1P,   g_g1);
    cudaGetSymbolAddress((void**)&hwP,   g_hw);
    cudaGetSymbolAddress((void**)&h216P, g_h216);
    cudaGetSymbolAddress((void**)&g2P,   g_g2);
    cudaGetSymbolAddress((void**)&hw2P,  g_hw2);
    cudaGetSymbolAddress((void**)&dinvP, g_dinv);
    cudaGetSymbolAddress((void**)&degP,  g_deg);
    cudaGetSymbolAddress((void**)&dstcP, g_dstc);
    cudaGetSymbolAddress((void**)&offP,  g_off);
    cudaGetSymbolAddress((void**)&curP,  g_cur);
    cudaGetSymbolAddress((void**)&esrcP, g_esrc);
    cudaGetSymbolAddress((void**)&ewP,   g_ew);

    // --- CSR build (by dst) + dinv ---
    zero_cnt_kernel<<<(NNODE + 255) / 256, 256>>>(degP, dstcP);
    cnt_kernel<<<(NEDGE + 255) / 256, 256>>>(src, dst, degP, dstcP);
    dinv_kernel<<<(NNODE + 255) / 256, 256>>>(degP, dinvP);
    scan_kernel<<<1, 1024>>>(dstcP, offP, curP);
    fill_kernel<<<(NEDGE + 255) / 256, 256>>>(src, dst, dinvP, curP, esrcP, ewP);

    // --- weight prep (fp16) ---
    {
        dim3 grid((NNODE + 31) / 32, INC / 32);
        transpose_wt_kernel<<<grid, dim3(32, 8)>>>(Wt, wttP);
    }
    wconv_kernel<<<(INC * HID + 255) / 256, 256>>>(W1_1, bt1P, INC, HID, 0);
    wconv_kernel<<<(INC * HID + 255) / 256, 256>>>(W0_1, bt0P, INC, HID, 0);
    wconv_kernel<<<(HID * OUTC + 255) / 256, 256>>>(W1_mu, bt2gP, HID, OUTC, 0);
    wconv_kernel<<<(HID * OUTC + 255) / 256, 256>>>(W1_ls, bt2gP, HID, OUTC, OUTC);
    wconv_kernel<<<(HID * OUTC + 255) / 256, 256>>>(W0_mu, bt2hP, HID, OUTC, 0);
    wconv_kernel<<<(HID * OUTC + 255) / 256, 256>>>(W0_ls, bt2hP, HID, OUTC, OUTC);

    // --- h16 = relu(x @ Wt + bt) via mma.sync fp16, BK=32 ---
    {
        cudaFuncSetAttribute(gemm_big_mma,
                             cudaFuncAttributeMaxDynamicSharedMemorySize, GSMEM_TOTAL);
        gemm_big_mma<<<NNODE / BM, 256, GSMEM_TOTAL>>>(x, wttP, bt, h16P);
    }
    // --- g1 = h@W1_1 ; hw = h@W0_1  (mma) ---
    sgemm_mma<INC><<<dim3(NNODE / SBM, 2), 128>>>(h16P, bt1P, bt0P, g1P, hwP);
    // --- h2 = relu(hw + gather(w*g1) + b1) -> fp16  (fused) ---
    gather_h2_kernel<<<(NNODE + 7) / 8, 256>>>(offP, esrcP, ewP, g1P, hwP, b1, h216P);
    // --- g2 = h2@[W1mu|W1ls] ; hw2 = h2@[W0mu|W0ls]  (mma) ---
    sgemm_mma<HID><<<dim3(NNODE / SBM, 2), 128>>>(h216P, bt2gP, bt2hP, g2P, hw2P);
    // --- out = hw2 + gather(w*g2) + bias  (fused) ---
    gather_out_kernel<<<(NNODE + 7) / 8, 256>>>(offP, esrcP, ewP, g2P, hw2P, b_mu, b_ls, out);
}

// round 16
// speedup vs baseline: 5.5979x; 1.0452x over previous
#include <cuda_runtime.h>
#include <cuda_fp16.h>
#include <cstdint>

#define NNODE 10000
#define KPAD  10016     // padded K stride for WtT (pad bytes never written -> zero)
#define INC   256
#define HID   128      // 2*OUT_C
#define OUTC  64
#define NEDGE 640000

// ---- big GEMM tiling (mma.sync fp16, m16n8k16, BK=32) ----
#define BM 80
#define BK 32
#define NKT ((NNODE + BK - 1) / BK)   // 313 (last iter: 16 valid k, rest zero-padded)
#define A_BYTES (BM * BK * 2)     // 5120 (fp16)
#define B_BYTES (INC * BK * 2)    // 16384 (fp16)
#define STAGE_BYTES (A_BYTES + B_BYTES)     // 21504
#define NSTAGE 4
#define GSMEM_TOTAL (NSTAGE * STAGE_BYTES)  // 86016

// ---- small GEMM tiling ----
#define SBM 80
#define SBN 128
#define SA_BYTES (SBM * 16 * 2)            // 2560
#define SB_BYTES (SBN * 16 * 2)            // 4096
#define SSTAGE (SA_BYTES + SB_BYTES)       // 6656

// ---------------- scratch (device globals; no allocations allowed) ----------
__device__ __half g_h16 [NNODE * INC];  // relu(x@Wt+bt) fp16
__device__ __half g_WtT [INC * KPAD];   // Wt transposed (K-major, padded), fp16
__device__ __half g_BT1 [HID * INC];    // W1_1^T fp16  [n][k]
__device__ __half g_BT0 [HID * INC];    // W0_1^T fp16
__device__ __half g_BT2g[HID * HID];    // [W1_mu|W1_ls]^T fp16
__device__ __half g_BT2h[HID * HID];    // [W0_mu|W0_ls]^T fp16
__device__ __half g_g1 [NNODE * HID];   // h @ W1_1           (fp16)
__device__ __half g_hw [NNODE * HID];   // h @ W0_1           (fp16)
__device__ __half g_h216[NNODE * HID];  // relu(hw + s1 + b1) (fp16)
__device__ __half g_g2 [NNODE * HID];   // [h2@W1_mu | h2@W1_ls] (fp16)
__device__ __half g_hw2[NNODE * HID];   // [h2@W0_mu | h2@W0_ls] (fp16)
__device__ float  g_dinv[NNODE];
__device__ int    g_deg [NNODE];
__device__ int    g_dstc[NNODE];
__device__ int    g_off [NNODE + 1];
__device__ int    g_cur [NNODE];
__device__ int    g_esrc[NEDGE];
__device__ float  g_ew  [NEDGE];

// ======================= helpers ============================================
__device__ __forceinline__ uint32_t smem_u32(const void* p) {
    uint32_t a;
    asm("{ .reg .u64 t; cvta.to.shared.u64 t, %1; cvt.u32.u64 %0, t; }" : "=r"(a) : "l"(p));
    return a;
}
__device__ __forceinline__ void cp_async16(uint32_t dst, const void* src) {
    asm volatile("cp.async.cg.shared.global [%0], [%1], 16;" :: "r"(dst), "l"(src));
}
#define CP_COMMIT() asm volatile("cp.async.commit_group;" ::: "memory")
#define CP_WAIT2()  asm volatile("cp.async.wait_group 2;" ::: "memory")
#define CP_WAIT1()  asm volatile("cp.async.wait_group 1;" ::: "memory")

__device__ __forceinline__ void ldsm4(uint32_t& r0, uint32_t& r1, uint32_t& r2, uint32_t& r3,
                                      uint32_t addr) {
    asm volatile("ldmatrix.sync.aligned.m8n8.x4.shared.b16 {%0,%1,%2,%3}, [%4];"
                 : "=r"(r0), "=r"(r1), "=r"(r2), "=r"(r3) : "r"(addr));
}
__device__ __forceinline__ void mma_f16(float* c, uint32_t a0, uint32_t a1, uint32_t a2,
                                        uint32_t a3, uint32_t b0, uint32_t b1) {
    asm volatile("mma.sync.aligned.m16n8k16.row.col.f32.f16.f16.f32 "
                 "{%0,%1,%2,%3}, {%4,%5,%6,%7}, {%8,%9}, {%0,%1,%2,%3};"
                 : "+f"(c[0]), "+f"(c[1]), "+f"(c[2]), "+f"(c[3])
                 : "r"(a0), "r"(a1), "r"(a2), "r"(a3), "r"(b0), "r"(b1));
}
__device__ __forceinline__ float4 h4_to_f4(uint2 u) {
    __half2 a = *(__half2*)&u.x, b = *(__half2*)&u.y;
    float2 fa = __half22float2(a), fb = __half22float2(b);
    return make_float4(fa.x, fa.y, fb.x, fb.y);
}

// ---------------- CSR build --------------------------------------------------
__global__ void zero_cnt_kernel(int* deg, int* dstc) {
    int i = blockIdx.x * blockDim.x + threadIdx.x;
    if (i < NNODE) { deg[i] = 0; dstc[i] = 0; }
}
__global__ void cnt_kernel(const int* __restrict__ src, const int* __restrict__ dst,
                           int* __restrict__ deg, int* __restrict__ dstc) {
    int e = blockIdx.x * blockDim.x + threadIdx.x;
    if (e < NEDGE) {
        atomicAdd(&deg[src[e]], 1);
        atomicAdd(&dstc[dst[e]], 1);
    }
}
// single-block exclusive scan over dstc -> off/cursor, plus dinv from deg
__global__ __launch_bounds__(1024) void scan_kernel(
    const int* __restrict__ cnt, int* __restrict__ off, int* __restrict__ cursor,
    const int* __restrict__ deg, float* __restrict__ dinv)
{
    __shared__ int sbuf[NNODE];
    __shared__ int wsum[32];
    const int tid = threadIdx.x;
    const int lane = tid & 31, wid = tid >> 5;
    for (int i = tid; i < NNODE; i += 1024) {
        sbuf[i] = cnt[i];
        int d = deg[i];
        dinv[i] = (d > 0) ? rsqrtf((float)d) : 0.f;
    }
    __syncthreads();

    const int CH = (NNODE + 1023) / 1024;   // 10
    int base = tid * CH;
    int local[CH];
    int sum = 0;
#pragma unroll
    for (int j = 0; j < CH; j++) {
        int i = base + j;
        int v = (i < NNODE) ? sbuf[i] : 0;
        local[j] = sum;
        sum += v;
    }
    int inc = sum;
#pragma unroll
    for (int d = 1; d < 32; d <<= 1) {
        int v = __shfl_up_sync(0xffffffffu, inc, d);
        if (lane >= d) inc += v;
    }
    if (lane == 31) wsum[wid] = inc;
    __syncthreads();
    if (wid == 0) {
        int w = wsum[lane];
        int wi = w;
#pragma unroll
        for (int d = 1; d < 32; d <<= 1) {
            int v = __shfl_up_sync(0xffffffffu, wi, d);
            if (lane >= d) wi += v;
        }
        wsum[lane] = wi - w;
    }
    __syncthreads();
    int pre = wsum[wid] + (inc - sum);
#pragma unroll
    for (int j = 0; j < CH; j++) {
        int i = base + j;
        if (i < NNODE) sbuf[i] = pre + local[j];
    }
    __syncthreads();
    for (int i = tid; i < NNODE; i += 1024) {
        int o = sbuf[i];
        off[i] = o;
        cursor[i] = o;
    }
    if (tid == 1023) off[NNODE] = pre + sum;
}
__global__ void fill_kernel(const int* __restrict__ src, const int* __restrict__ dst,
                            const float* __restrict__ dinv, int* __restrict__ cursor,
                            int* __restrict__ esrc, float* __restrict__ ew) {
    int e = blockIdx.x * blockDim.x + threadIdx.x;
    if (e < NEDGE) {
        int s = src[e], d = dst[e];
        int pos = atomicAdd(&cursor[d], 1);
        esrc[pos] = s;
        ew[pos] = -dinv[s] * dinv[d];
    }
}

// ---------------- fused gather #1: h2 = relu(hw + gather(w*g1) + b1) -> fp16 -
// G, HW fp16 rows of 128 (256B); lane handles 4 cols (uint2 = 2 half2).
__global__ void gather_h2_kernel(const int* __restrict__ off, const int* __restrict__ esrc,
                                 const float* __restrict__ ew, const __half* __restrict__ G,
                                 const __half* __restrict__ HW, const float* __restrict__ b1,
                                 __half* __restrict__ H2)
{
    int node = blockIdx.x * 8 + (threadIdx.x >> 5);
    int lane = threadIdx.x & 31;
    if (node >= NNODE) return;
    int beg = off[node], end = off[node + 1];
    const uint2* G2 = (const uint2*)G;
    float4 acc = make_float4(0.f, 0.f, 0.f, 0.f);
    for (int base = beg; base < end; base += 32) {
        int idx = base + lane;
        int   se = 0;
        float we = 0.f;
        if (idx < end) { se = __ldg(&esrc[idx]); we = __ldg(&ew[idx]); }
        int n = min(32, end - base);
        for (int j = 0; j < n; j++) {
            int   sj = __shfl_sync(0xffffffffu, se, j);
            float wj = __shfl_sync(0xffffffffu, we, j);
            float4 v = h4_to_f4(__ldg(&G2[sj * 32 + lane]));
            acc.x += wj * v.x; acc.y += wj * v.y;
            acc.z += wj * v.z; acc.w += wj * v.w;
        }
    }
    float4 h = h4_to_f4(((const uint2*)HW)[node * 32 + lane]);
    float4 b = ((const float4*)b1)[lane];
    __half2 p0 = __floats2half2_rn(fmaxf(acc.x + h.x + b.x, 0.f),
                                   fmaxf(acc.y + h.y + b.y, 0.f));
    __half2 p1 = __floats2half2_rn(fmaxf(acc.z + h.z + b.z, 0.f),
                                   fmaxf(acc.w + h.w + b.w, 0.f));
    uint2 u;
    u.x = *(uint32_t*)&p0; u.y = *(uint32_t*)&p1;
    ((uint2*)H2)[node * 32 + lane] = u;
}

// ---------------- fused gather #2: out = hw2 + gather(w*g2) + bias ----------
__global__ void gather_out_kernel(const int* __restrict__ off, const int* __restrict__ esrc,
                                  const float* __restrict__ ew, const __half* __restrict__ G,
                                  const __half* __restrict__ HW2,
                                  const float* __restrict__ bmu, const float* __restrict__ bls,
                                  float* __restrict__ out)
{
    int node = blockIdx.x * 8 + (threadIdx.x >> 5);
    int lane = threadIdx.x & 31;
    if (node >= NNODE) return;
    int beg = off[node], end = off[node + 1];
    const uint2* G2 = (const uint2*)G;
    float4 acc = make_float4(0.f, 0.f, 0.f, 0.f);
    for (int base = beg; base < end; base += 32) {
        int idx = base + lane;
        int   se = 0;
        float we = 0.f;
        if (idx < end) { se = __ldg(&esrc[idx]); we = __ldg(&ew[idx]); }
        int n = min(32, end - base);
        for (int j = 0; j < n; j++) {
            int   sj = __shfl_sync(0xffffffffu, se, j);
            float wj = __shfl_sync(0xffffffffu, we, j);
            float4 v = h4_to_f4(__ldg(&G2[sj * 32 + lane]));
            acc.x += wj * v.x; acc.y += wj * v.y;
            acc.z += wj * v.z; acc.w += wj * v.w;
        }
    }
    float4 h = h4_to_f4(((const uint2*)HW2)[node * 32 + lane]);
    int hf = lane >> 4;          // 0 = mu cols, 1 = logstd cols
    int c4 = lane & 15;
    const float4* bp = hf ? (const float4*)bls : (const float4*)bmu;
    float4 b = bp[c4];
    float4 o;
    o.x = acc.x + h.x + b.x; o.y = acc.y + h.y + b.y;
    o.z = acc.z + h.z + b.z; o.w = acc.w + h.w + b.w;
    ((float4*)(out + (size_t)hf * NNODE * OUTC))[node * 16 + c4] = o;
}

// ---------------- Wt transpose -> fp16 K-major (padded stride) ---------------
__global__ void transpose_wt_kernel(const float* __restrict__ Wt, __half* __restrict__ WtT) {
    __shared__ float t[32][33];
    int kb = blockIdx.x * 32, nb = blockIdx.y * 32;
    int x = threadIdx.x, y = threadIdx.y;     // block (32, 8)
#pragma unroll
    for (int j = 0; j < 32; j += 8) {
        int k = kb + y + j;
        t[y + j][x] = (k < NNODE) ? Wt[(size_t)k * INC + nb + x] : 0.f;
    }
    __syncthreads();
#pragma unroll
    for (int j = 0; j < 32; j += 8) {
        int k = kb + x;
        int n = nb + y + j;
        if (k < NNODE) WtT[(size_t)n * KPAD + k] = __float2half_rn(t[x][y + j]);
    }
}

// ---------------- merged small-weight transposes (6-in-1) --------------------
__global__ void wconv_all_kernel(
    const float* __restrict__ W11, const float* __restrict__ W01,
    const float* __restrict__ W1mu, const float* __restrict__ W1ls,
    const float* __restrict__ W0mu, const float* __restrict__ W0ls,
    __half* __restrict__ bt1, __half* __restrict__ bt0,
    __half* __restrict__ bt2g, __half* __restrict__ bt2h)
{
    int i = blockIdx.x * blockDim.x + threadIdx.x;
    if (i < 32768) {                 // W1_1 [256,128]
        int k = i >> 7, n = i & 127;
        bt1[n * INC + k] = __float2half_rn(W11[i]);
    } else if (i < 65536) {          // W0_1 [256,128]
        int j = i - 32768; int k = j >> 7, n = j & 127;
        bt0[n * INC + k] = __float2half_rn(W01[j]);
    } else if (i < 73728) {          // W1_mu [128,64]
        int j = i - 65536; int k = j >> 6, n = j & 63;
        bt2g[n * HID + k] = __float2half_rn(W1mu[j]);
    } else if (i < 81920) {          // W1_ls [128,64]
        int j = i - 73728; int k = j >> 6, n = j & 63;
        bt2g[(64 + n) * HID + k] = __float2half_rn(W1ls[j]);
    } else if (i < 90112) {          // W0_mu [128,64]
        int j = i - 81920; int k = j >> 6, n = j & 63;
        bt2h[n * HID + k] = __float2half_rn(W0mu[j]);
    } else if (i < 98304) {          // W0_ls [128,64]
        int j = i - 90112; int k = j >> 6, n = j & 63;
        bt2h[(64 + n) * HID + k] = __float2half_rn(W0ls[j]);
    }
}

// ---------------- big GEMM: h16 = relu(x @ Wt + bt), BK=32, 256 threads -----
extern __shared__ char g_dyn_smem[];

__global__ __launch_bounds__(256) void gemm_big_mma(
    const float* __restrict__ A, const __half* __restrict__ BT,
    const float* __restrict__ bias, __half* __restrict__ C)
{
    char* smem = g_dyn_smem;
    const uint32_t sbase = smem_u32(smem);
    const int tid  = threadIdx.x;
    const int lane = tid & 31;
    const int w    = tid >> 5;           // 0..7
    const int row0 = blockIdx.x * BM;

    float c[5][4][4];
#pragma unroll
    for (int i = 0; i < 5; i++)
#pragma unroll
        for (int j = 0; j < 4; j++)
#pragma unroll
            for (int q = 0; q < 4; q++) c[i][j][q] = 0.f;

    float4 ra0[2], ra1[2];
    const int c0r = tid >> 2, c0k = tid & 3;
    const int c1  = 256 + tid;
    const int c1r = c1 >> 2, c1k = c1 & 3;
    const bool own1 = (tid < 64);

    auto ldgA = [&](int k0) {
        {
            int kk = k0 + c0k * 8;
            if (kk + 8 <= NNODE) {
                const float* p = A + (size_t)(row0 + c0r) * NNODE + kk;
                ra0[0] = *(const float4*)p;
                ra0[1] = *(const float4*)(p + 4);
            } else {
                ra0[0] = make_float4(0.f,0.f,0.f,0.f);
                ra0[1] = make_float4(0.f,0.f,0.f,0.f);
            }
        }
        if (own1) {
            int kk = k0 + c1k * 8;
            if (kk + 8 <= NNODE) {
                const float* p = A + (size_t)(row0 + c1r) * NNODE + kk;
                ra1[0] = *(const float4*)p;
                ra1[1] = *(const float4*)(p + 4);
            } else {
                ra1[0] = make_float4(0.f,0.f,0.f,0.f);
                ra1[1] = make_float4(0.f,0.f,0.f,0.f);
            }
        }
    };
    auto cvt16 = [](float4 v0, float4 v1) {
        __half2 h0 = __floats2half2_rn(v0.x, v0.y);
        __half2 h1 = __floats2half2_rn(v0.z, v0.w);
        __half2 h2 = __floats2half2_rn(v1.x, v1.y);
        __half2 h3 = __floats2half2_rn(v1.z, v1.w);
        uint4 u;
        u.x = *(uint32_t*)&h0; u.y = *(uint32_t*)&h1;
        u.z = *(uint32_t*)&h2; u.w = *(uint32_t*)&h3;
        return u;
    };
    auto stsA = [&](int stage) {
        char* base = smem + stage * STAGE_BYTES;
        {
            int s = c0k ^ ((c0r >> 1) & 3);
            *(uint4*)(base + c0r * 64 + s * 16) = cvt16(ra0[0], ra0[1]);
        }
        if (own1) {
            int s = c1k ^ ((c1r >> 1) & 3);
            *(uint4*)(base + c1r * 64 + s * 16) = cvt16(ra1[0], ra1[1]);
        }
    };
    auto cpB = [&](int stage, int k0) {
        uint32_t base = sbase + stage * STAGE_BYTES + A_BYTES;
#pragma unroll
        for (int it = 0; it < 4; it++) {
            int i  = tid + it * 256;
            int n  = i >> 2;
            int kc = i & 3;
            int s  = kc ^ ((n >> 1) & 3);
            cp_async16(base + (uint32_t)(n * 64 + s * 16),
                       BT + (size_t)n * KPAD + k0 + kc * 8);
        }
    };

    const int a_row  = (lane & 7) + ((lane >> 3) & 1) * 8;
    const int a_c    = (lane >> 4) & 1;
    const int b_nl   = (lane & 7) + ((lane >> 4) & 1) * 8;
    const int b_c    = (lane >> 3) & 1;

    // ---- prologue ----
    cpB(0, 0);          CP_COMMIT();
    cpB(1, 1 * BK);     CP_COMMIT();
    cpB(2, 2 * BK);     CP_COMMIT();
    ldgA(0);            stsA(0);
    ldgA(1 * BK);       stsA(1);
    ldgA(2 * BK);       stsA(2);
    ldgA(3 * BK);                    // held for stage 3 (stored at kt=0)

    for (int kt = 0; kt < NKT; kt++) {
        CP_WAIT2();
        __syncthreads();

        const int kn = kt + 3;
        if (kn < NKT) {
            cpB(kn & 3, kn * BK);
            stsA(kn & 3);
        }
        CP_COMMIT();
        if (kt + 4 < NKT) ldgA((kt + 4) * BK);

        const uint32_t abase = sbase + (uint32_t)(kt & 3) * STAGE_BYTES;
        const uint32_t bbase = abase + A_BYTES;

#pragma unroll
        for (int ks = 0; ks < 2; ks++) {
            uint32_t bb[2][4];
#pragma unroll
            for (int np = 0; np < 2; np++) {
                int n = w * 32 + np * 16 + b_nl;
                int s = (ks * 2 + b_c) ^ ((n >> 1) & 3);
                ldsm4(bb[np][0], bb[np][1], bb[np][2], bb[np][3],
                      bbase + (uint32_t)(n * 64 + s * 16));
            }
#pragma unroll
            for (int mf = 0; mf < 5; mf++) {
                int r = mf * 16 + a_row;
                int s = (ks * 2 + a_c) ^ ((r >> 1) & 3);
                uint32_t a0, a1, a2, a3;
                ldsm4(a0, a1, a2, a3, abase + (uint32_t)(r * 64 + s * 16));
#pragma unroll
                for (int np = 0; np < 2; np++) {
                    mma_f16(c[mf][np * 2],     a0, a1, a2, a3, bb[np][0], bb[np][1]);
                    mma_f16(c[mf][np * 2 + 1], a0, a1, a2, a3, bb[np][2], bb[np][3]);
                }
            }
        }
    }

    // epilogue: bias + relu -> fp16
    const int g = lane >> 2;
    const int t2 = (lane & 3) * 2;
#pragma unroll
    for (int mf = 0; mf < 5; mf++) {
        int r = row0 + mf * 16 + g;
#pragma unroll
        for (int nf = 0; nf < 4; nf++) {
            int col = w * 32 + nf * 8 + t2;
            float2 bb = *(const float2*)(bias + col);
            __half2 p0 = __floats2half2_rn(fmaxf(c[mf][nf][0] + bb.x, 0.f),
                                           fmaxf(c[mf][nf][1] + bb.y, 0.f));
            __half2 p1 = __floats2half2_rn(fmaxf(c[mf][nf][2] + bb.x, 0.f),
                                           fmaxf(c[mf][nf][3] + bb.y, 0.f));
            *(__half2*)(C + (size_t)r * INC + col)       = p0;
            *(__half2*)(C + (size_t)(r + 8) * INC + col) = p1;
        }
    }
}

// ---------------- small GEMM via mma.sync fp16 (fp16 output) -----------------
template<int KK>
__global__ __launch_bounds__(128) void sgemm_mma(
    const __half* __restrict__ A,
    const __half* __restrict__ BTa, const __half* __restrict__ BTb,
    __half* __restrict__ Ca, __half* __restrict__ Cb)
{
    __shared__ char smem[3 * SSTAGE];
    const uint32_t sbase = smem_u32(smem);
    const int tid  = threadIdx.x;
    const int lane = tid & 31;
    const int w    = tid >> 5;
    const int row0 = blockIdx.x * SBM;
    const __half* BT = blockIdx.y ? BTb : BTa;
    __half* C = blockIdx.y ? Cb : Ca;
    const int SNKT = KK / 16;

    float c[5][4][4];
#pragma unroll
    for (int i = 0; i < 5; i++)
#pragma unroll
        for (int j = 0; j < 4; j++)
#pragma unroll
            for (int q = 0; q < 4; q++) c[i][j][q] = 0.f;

    auto ld_stage = [&](int stage, int kt) {
        uint32_t abase = sbase + (uint32_t)stage * SSTAGE;
        uint32_t bbase = abase + SA_BYTES;
        int k0 = kt * 16;
#pragma unroll
        for (int it = 0; it < 4; it++) {
            int i = tid + it * 128;
            if (i < 160) {
                int r = i >> 1, kc = i & 1;
                int s = kc ^ ((r >> 2) & 1);
                cp_async16(abase + (uint32_t)(r * 32 + s * 16),
                           A + (size_t)(row0 + r) * KK + k0 + kc * 8);
            } else if (i < 416) {
                int j = i - 160;
                int n = j >> 1, kc = j & 1;
                int s = kc ^ ((n >> 2) & 1);
                cp_async16(bbase + (uint32_t)(n * 32 + s * 16),
                           BT + (size_t)n * KK + k0 + kc * 8);
            }
        }
    };

    const int a_row  = (lane & 7) + ((lane >> 3) & 1) * 8;
    const int a_c    = (lane >> 4) & 1;
    const int b_nl   = (lane & 7) + ((lane >> 4) & 1) * 8;
    const int b_c    = (lane >> 3) & 1;

    ld_stage(0, 0); CP_COMMIT();
    ld_stage(1, 1); CP_COMMIT();

    for (int kt = 0; kt < SNKT; kt++) {
        CP_WAIT1();
        __syncthreads();
        if (kt + 2 < SNKT) ld_stage((kt + 2) % 3, kt + 2);
        CP_COMMIT();

        const uint32_t abase = sbase + (uint32_t)(kt % 3) * SSTAGE;
        const uint32_t bbase = abase + SA_BYTES;

        uint32_t bb[2][4];
#pragma unroll
        for (int np = 0; np < 2; np++) {
            int n = w * 32 + np * 16 + b_nl;
            int s = b_c ^ ((n >> 2) & 1);
            ldsm4(bb[np][0], bb[np][1], bb[np][2], bb[np][3],
                  bbase + (uint32_t)(n * 32 + s * 16));
        }
#pragma unroll
        for (int mf = 0; mf < 5; mf++) {
            int r = mf * 16 + a_row;
            int s = a_c ^ ((r >> 2) & 1);
            uint32_t a0, a1, a2, a3;
            ldsm4(a0, a1, a2, a3, abase + (uint32_t)(r * 32 + s * 16));
#pragma unroll
            for (int np = 0; np < 2; np++) {
                mma_f16(c[mf][np * 2],     a0, a1, a2, a3, bb[np][0], bb[np][1]);
                mma_f16(c[mf][np * 2 + 1], a0, a1, a2, a3, bb[np][2], bb[np][3]);
            }
        }
    }

    const int g = lane >> 2;
    const int t2 = (lane & 3) * 2;
#pragma unroll
    for (int mf = 0; mf < 5; mf++) {
        int r = row0 + mf * 16 + g;
#pragma unroll
        for (int nf = 0; nf < 4; nf++) {
            int col = w * 32 + nf * 8 + t2;
            __half2 o0 = __floats2half2_rn(c[mf][nf][0], c[mf][nf][1]);
            __half2 o1 = __floats2half2_rn(c[mf][nf][2], c[mf][nf][3]);
            *(__half2*)(C + (size_t)r * HID + col)       = o0;
            *(__half2*)(C + (size_t)(r + 8) * HID + col) = o1;
        }
    }
}

// ---------------- launch -----------------------------------------------------
extern "C" void kernel_launch(void* const* d_in, const int* in_sizes, int n_in,
                              void* d_out, int out_size)
{
    const float* x     = (const float*)d_in[0];
    const int*   ei    = (const int*)  d_in[1];
    const float* Wt    = (const float*)d_in[2];
    const float* bt    = (const float*)d_in[3];
    const float* W0_1  = (const float*)d_in[4];
    const float* W1_1  = (const float*)d_in[5];
    const float* b1    = (const float*)d_in[6];
    const float* W0_mu = (const float*)d_in[7];
    const float* W1_mu = (const float*)d_in[8];
    const float* b_mu  = (const float*)d_in[9];
    const float* W0_ls = (const float*)d_in[10];
    const float* W1_ls = (const float*)d_in[11];
    const float* b_ls  = (const float*)d_in[12];
    float* out = (float*)d_out;

    const int* src = ei;
    const int* dst = ei + NEDGE;

    float *dinvP, *ewP;
    __half *h16P, *wttP, *bt1P, *bt0P, *bt2gP, *bt2hP, *g1P, *hwP, *h216P, *g2P, *hw2P;
    int *degP, *dstcP, *offP, *curP, *esrcP;
    cudaGetSymbolAddress((void**)&h16P,  g_h16);
    cudaGetSymbolAddress((void**)&wttP,  g_WtT);
    cudaGetSymbolAddress((void**)&bt1P,  g_BT1);
    cudaGetSymbolAddress((void**)&bt0P,  g_BT0);
    cudaGetSymbolAddress((void**)&bt2gP, g_BT2g);
    cudaGetSymbolAddress((void**)&bt2hP, g_BT2h);
    cudaGetSymbolAddress((void**)&g1P,   g_g1);
    cudaGetSymbolAddress((void**)&hwP,   g_hw);
    cudaGetSymbolAddress((void**)&h216P, g_h216);
    cudaGetSymbolAddress((void**)&g2P,   g_g2);
    cudaGetSymbolAddress((void**)&hw2P,  g_hw2);
    cudaGetSymbolAddress((void**)&dinvP, g_dinv);
    cudaGetSymbolAddress((void**)&degP,  g_deg);
    cudaGetSymbolAddress((void**)&dstcP, g_dstc);
    cudaGetSymbolAddress((void**)&offP,  g_off);
    cudaGetSymbolAddress((void**)&curP,  g_cur);
    cudaGetSymbolAddress((void**)&esrcP, g_esrc);
    cudaGetSymbolAddress((void**)&ewP,   g_ew);

    // --- CSR build (by dst) + dinv ---
    zero_cnt_kernel<<<(NNODE + 255) / 256, 256>>>(degP, dstcP);
    cnt_kernel<<<(NEDGE + 255) / 256, 256>>>(src, dst, degP, dstcP);
    scan_kernel<<<1, 1024>>>(dstcP, offP, curP, degP, dinvP);
    fill_kernel<<<(NEDGE + 255) / 256, 256>>>(src, dst, dinvP, curP, esrcP, ewP);

    // --- weight prep (fp16) ---
    {
        dim3 grid((NNODE + 31) / 32, INC / 32);
        transpose_wt_kernel<<<grid, dim3(32, 8)>>>(Wt, wttP);
    }
    wconv_all_kernel<<<(98304 + 255) / 256, 256>>>(W1_1, W0_1, W1_mu, W1_ls, W0_mu, W0_ls,
                                                   bt1P, bt0P, bt2gP, bt2hP);

    // --- h16 = relu(x @ Wt + bt) via mma.sync fp16, BK=32 ---
    {
        cudaFuncSetAttribute(gemm_big_mma,
                             cudaFuncAttributeMaxDynamicSharedMemorySize, GSMEM_TOTAL);
        gemm_big_mma<<<NNODE / BM, 256, GSMEM_TOTAL>>>(x, wttP, bt, h16P);
    }
    // --- g1 = h@W1_1 ; hw = h@W0_1  (mma, fp16 out) ---
    sgemm_mma<INC><<<dim3(NNODE / SBM, 2), 128>>>(h16P, bt1P, bt0P, g1P, hwP);
    // --- h2 = relu(hw + gather(w*g1) + b1) -> fp16  (fused) ---
    gather_h2_kernel<<<(NNODE + 7) / 8, 256>>>(offP, esrcP, ewP, g1P, hwP, b1, h216P);
    // --- g2 = h2@[W1mu|W1ls] ; hw2 = h2@[W0mu|W0ls]  (mma, fp16 out) ---
    sgemm_mma<HID><<<dim3(NNODE / SBM, 2), 128>>>(h216P, bt2gP, bt2hP, g2P, hw2P);
    // --- out = hw2 + gather(w*g2) + bias  (fused) ---
    gather_out_kernel<<<(NNODE + 7) / 8, 256>>>(offP, esrcP, ewP, g2P, hw2P, b_mu, b_ls, out);
}